// round 1
// baseline (speedup 1.0000x reference)
#include <cuda_runtime.h>
#include <cuda_bf16.h>
#include <math.h>

// Problem constants
#define BB 4
#define TT 1024
#define DD 1024
#define HH 16
#define HD 64
#define ROWS (BB * TT)        // 4096
#define QKV_N (3 * DD)        // 3072

// Scratch (allocation-free: __device__ globals)
__device__ float g_qkv[ROWS * QKV_N];   // [4096, 3072]
__device__ float g_ctx[ROWS * DD];      // [4096, 1024]

// ---------------------------------------------------------------------------
// SGEMM: C[M,N] = A[M,K] @ B[K,N], all row-major, M%128==0, N%128==0, K%8==0
// 128x128 block tile, BK=8, 256 threads, 8x8 micro-tile per thread.
// ---------------------------------------------------------------------------
__global__ void __launch_bounds__(256) sgemm128(
    const float* __restrict__ A, const float* __restrict__ B,
    float* __restrict__ C, int M, int N, int K)
{
    __shared__ float As[8][128];
    __shared__ float Bs[8][128];

    const int tid = threadIdx.x;
    const int block_row = blockIdx.y * 128;
    const int block_col = blockIdx.x * 128;

    const int tr = tid >> 4;          // 0..15 (row group)
    const int tc = tid & 15;          // 0..15 (col group)

    // A tile load mapping: 128 rows x 8 cols = 1024 floats = 256 float4
    const int arow = tid >> 1;            // 0..127
    const int acol = (tid & 1) << 2;      // 0 or 4
    // B tile load mapping: 8 rows x 128 cols
    const int brow = tid >> 5;            // 0..7
    const int bcol = (tid & 31) << 2;     // 0..124

    const float* Aptr = A + (size_t)(block_row + arow) * K + acol;
    const float* Bptr = B + (size_t)brow * N + block_col + bcol;

    float acc[8][8];
#pragma unroll
    for (int i = 0; i < 8; i++)
#pragma unroll
        for (int j = 0; j < 8; j++) acc[i][j] = 0.f;

    for (int k0 = 0; k0 < K; k0 += 8) {
        float4 a4 = *(const float4*)(Aptr + k0);
        float4 b4 = *(const float4*)(Bptr + (size_t)k0 * N);

        As[acol + 0][arow] = a4.x;
        As[acol + 1][arow] = a4.y;
        As[acol + 2][arow] = a4.z;
        As[acol + 3][arow] = a4.w;
        *(float4*)&Bs[brow][bcol] = b4;
        __syncthreads();

#pragma unroll
        for (int kk = 0; kk < 8; kk++) {
            float a[8], b[8];
            *(float4*)(a)     = *(const float4*)&As[kk][tr * 8];
            *(float4*)(a + 4) = *(const float4*)&As[kk][tr * 8 + 4];
            *(float4*)(b)     = *(const float4*)&Bs[kk][tc * 8];
            *(float4*)(b + 4) = *(const float4*)&Bs[kk][tc * 8 + 4];
#pragma unroll
            for (int i = 0; i < 8; i++)
#pragma unroll
                for (int j = 0; j < 8; j++)
                    acc[i][j] += a[i] * b[j];
        }
        __syncthreads();
    }

#pragma unroll
    for (int i = 0; i < 8; i++) {
        const size_t row = (size_t)(block_row + tr * 8 + i);
        float* cp = C + row * N + block_col + tc * 8;
        float4 c0 = make_float4(acc[i][0], acc[i][1], acc[i][2], acc[i][3]);
        float4 c1 = make_float4(acc[i][4], acc[i][5], acc[i][6], acc[i][7]);
        *(float4*)(cp)     = c0;
        *(float4*)(cp + 4) = c1;
    }
}

// ---------------------------------------------------------------------------
// Fused causal attention (flash-style), one block = (q-tile of 64 rows, one b,h)
// grid = (T/64 = 16, B*H = 64), 256 threads (16x16), dynamic smem.
// qkv layout: [B*T, 3072] with q at col h*64, k at 1024+h*64, v at 2048+h*64.
// ctx layout: [B*T, 1024] with col h*64 + d.
// ---------------------------------------------------------------------------
#define PITCH 65
#define ATTN_SMEM (4 * 64 * PITCH * (int)sizeof(float))   // 66560 bytes

__global__ void __launch_bounds__(256) attn64(
    const float* __restrict__ qkv, float* __restrict__ ctx)
{
    extern __shared__ float sm[];
    float (*Qs)[PITCH] = (float(*)[PITCH])(sm);
    float (*Ks)[PITCH] = (float(*)[PITCH])(sm + 64 * PITCH);
    float (*Vs)[PITCH] = (float(*)[PITCH])(sm + 2 * 64 * PITCH);
    float (*Ps)[PITCH] = (float(*)[PITCH])(sm + 3 * 64 * PITCH);

    const int qi = blockIdx.x;          // 0..15
    const int bh = blockIdx.y;          // 0..63
    const int b  = bh >> 4;
    const int h  = bh & 15;

    const int tid = threadIdx.x;
    const int ty = tid >> 4;            // 0..15 -> rows ty*4..ty*4+3
    const int tx = tid & 15;            // 0..15 -> cols tx*4..tx*4+3
    const float scale = 0.125f;         // 1/sqrt(64)

    const float* base = qkv + (size_t)b * TT * QKV_N + h * HD;

    // Load Q tile [64 x 64]
    for (int idx = tid; idx < 64 * 64; idx += 256) {
        int r = idx >> 6, c = idx & 63;
        Qs[r][c] = base[(size_t)(qi * 64 + r) * QKV_N + c];
    }

    float m[4], l[4], acc[4][4];
#pragma unroll
    for (int a = 0; a < 4; a++) {
        m[a] = -INFINITY; l[a] = 0.f;
#pragma unroll
        for (int j = 0; j < 4; j++) acc[a][j] = 0.f;
    }

    for (int jt = 0; jt <= qi; jt++) {
        __syncthreads();   // previous iteration's reads done (also covers Q load)
        // Load K, V tiles [64 x 64]
        for (int idx = tid; idx < 64 * 64; idx += 256) {
            int r = idx >> 6, c = idx & 63;
            size_t rowoff = (size_t)(jt * 64 + r) * QKV_N;
            Ks[r][c] = base[rowoff + DD + c];
            Vs[r][c] = base[rowoff + 2 * DD + c];
        }
        __syncthreads();

        // S = Q K^T (4x4 per thread)
        float s[4][4];
#pragma unroll
        for (int a = 0; a < 4; a++)
#pragma unroll
            for (int j = 0; j < 4; j++) s[a][j] = 0.f;

        for (int d = 0; d < 64; d++) {
            float qv[4], kv[4];
#pragma unroll
            for (int a = 0; a < 4; a++) qv[a] = Qs[ty * 4 + a][d];
#pragma unroll
            for (int j = 0; j < 4; j++) kv[j] = Ks[tx * 4 + j][d];
#pragma unroll
            for (int a = 0; a < 4; a++)
#pragma unroll
                for (int j = 0; j < 4; j++)
                    s[a][j] += qv[a] * kv[j];
        }

        // scale + causal mask (only diagonal tile needs masking)
#pragma unroll
        for (int a = 0; a < 4; a++)
#pragma unroll
            for (int j = 0; j < 4; j++) {
                s[a][j] *= scale;
                if (jt == qi && (tx * 4 + j) > (ty * 4 + a))
                    s[a][j] = -INFINITY;
            }

        // Online softmax per row (rows owned by ty, reduce across 16 tx lanes)
#pragma unroll
        for (int a = 0; a < 4; a++) {
            float rm = fmaxf(fmaxf(s[a][0], s[a][1]), fmaxf(s[a][2], s[a][3]));
#pragma unroll
            for (int off = 8; off >= 1; off >>= 1)
                rm = fmaxf(rm, __shfl_xor_sync(0xffffffffu, rm, off));

            float mn = fmaxf(m[a], rm);
            float alpha = expf(m[a] - mn);     // expf(-inf - finite) = 0

            float rs = 0.f;
            float p[4];
#pragma unroll
            for (int j = 0; j < 4; j++) {
                p[j] = expf(s[a][j] - mn);
                rs += p[j];
            }
#pragma unroll
            for (int off = 8; off >= 1; off >>= 1)
                rs += __shfl_xor_sync(0xffffffffu, rs, off);

            l[a] = l[a] * alpha + rs;
            m[a] = mn;
#pragma unroll
            for (int j = 0; j < 4; j++) acc[a][j] *= alpha;

#pragma unroll
            for (int j = 0; j < 4; j++)
                Ps[ty * 4 + a][tx * 4 + j] = p[j];
        }
        __syncthreads();

        // O += P @ V  (thread owns rows ty*4.., head-dim cols tx*4..)
        for (int k = 0; k < 64; k++) {
            float pv[4], vv[4];
#pragma unroll
            for (int a = 0; a < 4; a++) pv[a] = Ps[ty * 4 + a][k];
#pragma unroll
            for (int j = 0; j < 4; j++) vv[j] = Vs[k][tx * 4 + j];
#pragma unroll
            for (int a = 0; a < 4; a++)
#pragma unroll
                for (int j = 0; j < 4; j++)
                    acc[a][j] += pv[a] * vv[j];
        }
    }

    // Normalize and write to ctx [B*T, 1024]
#pragma unroll
    for (int a = 0; a < 4; a++) {
        float inv = 1.f / l[a];
        int trow = qi * 64 + ty * 4 + a;
        float4 o = make_float4(acc[a][0] * inv, acc[a][1] * inv,
                               acc[a][2] * inv, acc[a][3] * inv);
        *(float4*)&ctx[((size_t)(b * TT + trow)) * DD + h * HD + tx * 4] = o;
    }
}

// ---------------------------------------------------------------------------
// Launch
// ---------------------------------------------------------------------------
extern "C" void kernel_launch(void* const* d_in, const int* in_sizes, int n_in,
                              void* d_out, int out_size)
{
    const float* x     = (const float*)d_in[0];   // [4,1024,1024]
    // d_in[1] = mask (int32, causal triu) — structure is known, unused
    const float* w_qkv = (const float*)d_in[2];   // [1024,3072]
    const float* w_out = (const float*)d_in[3];   // [1024,1024]
    float* out = (float*)d_out;                   // [4,1024,1024]

    float *qkv_p = nullptr, *ctx_p = nullptr;
    cudaGetSymbolAddress((void**)&qkv_p, g_qkv);
    cudaGetSymbolAddress((void**)&ctx_p, g_ctx);

    cudaFuncSetAttribute(attn64, cudaFuncAttributeMaxDynamicSharedMemorySize,
                         ATTN_SMEM);

    // 1) QKV projection: [4096,1024] @ [1024,3072]
    sgemm128<<<dim3(QKV_N / 128, ROWS / 128), 256>>>(x, w_qkv, qkv_p,
                                                     ROWS, QKV_N, DD);
    // 2) Fused causal attention
    attn64<<<dim3(TT / 64, BB * HH), 256, ATTN_SMEM>>>(qkv_p, ctx_p);
    // 3) Output projection: [4096,1024] @ [1024,1024]
    sgemm128<<<dim3(DD / 128, ROWS / 128), 256>>>(ctx_p, w_out, out,
                                                  ROWS, DD, DD);
}

// round 4
// speedup vs baseline: 1.5841x; 1.5841x over previous
#include <cuda_runtime.h>
#include <cuda_bf16.h>
#include <math.h>
#include <stdint.h>

// Problem constants
#define BB 4
#define TT 1024
#define DD 1024
#define HH 16
#define HD 64
#define ROWS (BB * TT)        // 4096
#define QKV_N (3 * DD)        // 3072

// ---------------------------------------------------------------------------
// Scratch (allocation-free: __device__ globals)
// ---------------------------------------------------------------------------
__device__ float g_qkv[ROWS * QKV_N];             // [4096, 3072] fp32
__device__ float g_ctx[ROWS * DD];                // [4096, 1024] fp32
__device__ __nv_bfloat16 g_xh[ROWS * DD];         // x hi/lo  [4096,1024]
__device__ __nv_bfloat16 g_xl[ROWS * DD];
__device__ __nv_bfloat16 g_wqh[QKV_N * DD];       // w_qkv^T hi/lo [3072,1024]
__device__ __nv_bfloat16 g_wql[QKV_N * DD];
__device__ __nv_bfloat16 g_woh[DD * DD];          // w_out^T hi/lo [1024,1024]
__device__ __nv_bfloat16 g_wol[DD * DD];
__device__ __nv_bfloat16 g_ch[ROWS * DD];         // ctx hi/lo [4096,1024]
__device__ __nv_bfloat16 g_cl[ROWS * DD];

// ---------------------------------------------------------------------------
// Baseline-PTX helpers (sm_80-class features only: cp.async, ldmatrix, HMMA)
// ---------------------------------------------------------------------------
__device__ __forceinline__ uint32_t smem_u32(const void* p) {
    uint32_t a;
    asm("{ .reg .u64 t; cvta.to.shared.u64 t, %1; cvt.u32.u64 %0, t; }"
        : "=r"(a) : "l"(p));
    return a;
}
__device__ __forceinline__ void cp_async16(uint32_t dst, const void* src) {
    asm volatile("cp.async.cg.shared.global [%0], [%1], 16;\n"
                 :: "r"(dst), "l"(src));
}
#define CP_COMMIT() asm volatile("cp.async.commit_group;" ::: "memory")
#define CP_WAIT(n)  asm volatile("cp.async.wait_group %0;" :: "n"(n) : "memory")

__device__ __forceinline__ void ldsm_x4(uint32_t* r, uint32_t addr) {
    asm volatile("ldmatrix.sync.aligned.m8n8.x4.shared.b16 {%0,%1,%2,%3}, [%4];"
                 : "=r"(r[0]), "=r"(r[1]), "=r"(r[2]), "=r"(r[3]) : "r"(addr));
}
__device__ __forceinline__ void mma16816(float* d, const uint32_t* a,
                                         const uint32_t* b) {
    asm volatile(
        "mma.sync.aligned.m16n8k16.row.col.f32.bf16.bf16.f32 "
        "{%0,%1,%2,%3}, {%4,%5,%6,%7}, {%8,%9}, {%0,%1,%2,%3};"
        : "+f"(d[0]), "+f"(d[1]), "+f"(d[2]), "+f"(d[3])
        : "r"(a[0]), "r"(a[1]), "r"(a[2]), "r"(a[3]), "r"(b[0]), "r"(b[1]));
}

// ---------------------------------------------------------------------------
// split kernels: fp32 -> (hi bf16, lo bf16)
// ---------------------------------------------------------------------------
__global__ void __launch_bounds__(256) split_rm(
    const float4* __restrict__ src, __nv_bfloat16* __restrict__ hi,
    __nv_bfloat16* __restrict__ lo, int n4)
{
    int i = blockIdx.x * blockDim.x + threadIdx.x;
    if (i >= n4) return;
    float4 v = src[i];
    __nv_bfloat16 h0 = __float2bfloat16(v.x);
    __nv_bfloat16 h1 = __float2bfloat16(v.y);
    __nv_bfloat16 h2 = __float2bfloat16(v.z);
    __nv_bfloat16 h3 = __float2bfloat16(v.w);
    __nv_bfloat16 l0 = __float2bfloat16(v.x - __bfloat162float(h0));
    __nv_bfloat16 l1 = __float2bfloat16(v.y - __bfloat162float(h1));
    __nv_bfloat16 l2 = __float2bfloat16(v.z - __bfloat162float(h2));
    __nv_bfloat16 l3 = __float2bfloat16(v.w - __bfloat162float(h3));
    __nv_bfloat162* hp = reinterpret_cast<__nv_bfloat162*>(hi) + 2 * i;
    __nv_bfloat162* lp = reinterpret_cast<__nv_bfloat162*>(lo) + 2 * i;
    hp[0] = __nv_bfloat162(h0, h1);  hp[1] = __nv_bfloat162(h2, h3);
    lp[0] = __nv_bfloat162(l0, l1);  lp[1] = __nv_bfloat162(l2, l3);
}

// transpose + split: src [K,N] fp32 -> dst [N,K] hi/lo bf16
__global__ void __launch_bounds__(256) split_tr(
    const float* __restrict__ src, __nv_bfloat16* __restrict__ hi,
    __nv_bfloat16* __restrict__ lo, int K, int N)
{
    __shared__ float t[32][33];
    int k0 = blockIdx.y * 32, n0 = blockIdx.x * 32;
    int tx = threadIdx.x, ty = threadIdx.y;      // (32, 8)
#pragma unroll
    for (int i = 0; i < 32; i += 8)
        t[ty + i][tx] = src[(size_t)(k0 + ty + i) * N + n0 + tx];
    __syncthreads();
#pragma unroll
    for (int i = 0; i < 32; i += 8) {
        float v = t[tx][ty + i];                 // src[k0+tx][n0+ty+i]
        __nv_bfloat16 h = __float2bfloat16(v);
        __nv_bfloat16 l = __float2bfloat16(v - __bfloat162float(h));
        size_t o = (size_t)(n0 + ty + i) * K + k0 + tx;
        hi[o] = h;
        lo[o] = l;
    }
}

// ---------------------------------------------------------------------------
// mma.sync split-bf16 GEMM: C[M,N] = A[M,K] @ Bt[N,K]^T  (fp32 out)
// CTA tile 128x128, BK=32, 8 warps (warp tile 32x64), 3-stage cp.async pipe.
// SMEM tiles stored K-major with 80B row pitch (conflict-free ldmatrix).
// ---------------------------------------------------------------------------
#define APITCH 80
#define TILE_BYTES (128 * APITCH)                 // 10240
#define STAGE_BYTES (4 * TILE_BYTES)              // Ah,Al,Bh,Bl = 40960
#define NSTAGE 3
#define GEMM_SMEM (NSTAGE * STAGE_BYTES)          // 122880

__global__ void __launch_bounds__(256) gemm_mma(
    const __nv_bfloat16* __restrict__ Ah, const __nv_bfloat16* __restrict__ Al,
    const __nv_bfloat16* __restrict__ Bh, const __nv_bfloat16* __restrict__ Bl,
    float* __restrict__ C, int M, int N, int K)
{
    extern __shared__ char dynsm[];
    const uint32_t sm0 = smem_u32(dynsm);

    const int tid  = threadIdx.x;
    const int wid  = tid >> 5;
    const int lane = tid & 31;
    const int m0 = blockIdx.y * 128;
    const int n0 = blockIdx.x * 128;

    const int warp_m = (wid & 3) * 32;     // 0,32,64,96
    const int warp_n = (wid >> 2) * 64;    // 0,64

    const int nch = K / 32;

    // loader: 2048 x 16B chunks per stage (4 tiles x 128 rows x 4 chunks)
    auto load_stage = [&](int kc, int stage) {
        const uint32_t sb = sm0 + stage * STAGE_BYTES;
        const int ke = kc * 32;
#pragma unroll
        for (int i = 0; i < 8; i++) {
            int t = tid + i * 256;
            int tile = t >> 9;               // 0..3
            int r = (t >> 2) & 127;
            int j = t & 3;
            uint32_t dst = sb + tile * TILE_BYTES + r * APITCH + j * 16;
            size_t goff;
            const __nv_bfloat16* src;
            if (tile == 0)      { src = Ah; goff = (size_t)(m0 + r) * K + ke + j * 8; }
            else if (tile == 1) { src = Al; goff = (size_t)(m0 + r) * K + ke + j * 8; }
            else if (tile == 2) { src = Bh; goff = (size_t)(n0 + r) * K + ke + j * 8; }
            else                { src = Bl; goff = (size_t)(n0 + r) * K + ke + j * 8; }
            cp_async16(dst, src + goff);
        }
        CP_COMMIT();
    };

    // per-warp ldmatrix base offsets (within a stage)
    // A (x4): rows m = warp_m + mt*16 + (lane&15), koff = ks*32 + (lane>>4)*16
    const uint32_t a_row = warp_m + (lane & 15);
    const uint32_t a_kof = (uint32_t)(lane >> 4) * 16;
    // B (x4 covers two n8 tiles): rows n = warp_n + p*16 + (lane&7) + (lane>>4)*8
    const uint32_t b_row = warp_n + (lane & 7) + ((lane >> 4) << 3);
    const uint32_t b_kof = (uint32_t)((lane >> 3) & 1) * 16;

    float acc[2][8][4];
#pragma unroll
    for (int mt = 0; mt < 2; mt++)
#pragma unroll
        for (int nt = 0; nt < 8; nt++)
#pragma unroll
            for (int e = 0; e < 4; e++) acc[mt][nt][e] = 0.f;

    load_stage(0, 0);
    load_stage(1, 1);

    for (int c = 0; c < nch; c++) {
        if (c + 1 < nch) { CP_WAIT(1); } else { CP_WAIT(0); }
        __syncthreads();

        // prefetch stage c+2 (buffer (c+2)%3 — last used by chunk c-1, now safe)
        if (c + 2 < nch) load_stage(c + 2, (c + 2) % NSTAGE);

        const uint32_t sb = sm0 + (c % NSTAGE) * STAGE_BYTES;
        const uint32_t aH = sb;
        const uint32_t aL = sb + TILE_BYTES;
        const uint32_t bH = sb + 2 * TILE_BYTES;
        const uint32_t bL = sb + 3 * TILE_BYTES;

#pragma unroll
        for (int ks = 0; ks < 2; ks++) {
            const uint32_t ks32 = ks * 32;
            uint32_t ah[2][4], al[2][4];
#pragma unroll
            for (int mt = 0; mt < 2; mt++) {
                uint32_t off = (a_row + mt * 16) * APITCH + ks32 + a_kof;
                ldsm_x4(ah[mt], aH + off);
                ldsm_x4(al[mt], aL + off);
            }
            uint32_t bh[8][2], bl[8][2];
#pragma unroll
            for (int p = 0; p < 4; p++) {
                uint32_t off = (b_row + p * 16) * APITCH + ks32 + b_kof;
                uint32_t q[4];
                ldsm_x4(q, bH + off);
                bh[2 * p][0] = q[0]; bh[2 * p][1] = q[1];
                bh[2 * p + 1][0] = q[2]; bh[2 * p + 1][1] = q[3];
                ldsm_x4(q, bL + off);
                bl[2 * p][0] = q[0]; bl[2 * p][1] = q[1];
                bl[2 * p + 1][0] = q[2]; bl[2 * p + 1][1] = q[3];
            }
#pragma unroll
            for (int mt = 0; mt < 2; mt++)
#pragma unroll
                for (int nt = 0; nt < 8; nt++) {
                    mma16816(acc[mt][nt], ah[mt], bh[nt]);
                    mma16816(acc[mt][nt], ah[mt], bl[nt]);
                    mma16816(acc[mt][nt], al[mt], bh[nt]);
                }
        }
        __syncthreads();
    }

    // epilogue: direct fp32 stores (float2 per fragment row)
    const int erow = m0 + warp_m + (lane >> 2);
    const int ecol = n0 + warp_n + (lane & 3) * 2;
#pragma unroll
    for (int mt = 0; mt < 2; mt++) {
#pragma unroll
        for (int nt = 0; nt < 8; nt++) {
            float* p0 = C + (size_t)(erow + mt * 16) * N + ecol + nt * 8;
            float* p1 = C + (size_t)(erow + mt * 16 + 8) * N + ecol + nt * 8;
            *(float2*)p0 = make_float2(acc[mt][nt][0], acc[mt][nt][1]);
            *(float2*)p1 = make_float2(acc[mt][nt][2], acc[mt][nt][3]);
        }
    }
}

// ---------------------------------------------------------------------------
// Fused causal attention (flash-style) — unchanged (passing, fp32)
// ---------------------------------------------------------------------------
#define PITCH 65
#define ATTN_SMEM (4 * 64 * PITCH * (int)sizeof(float))   // 66560 bytes

__global__ void __launch_bounds__(256) attn64(
    const float* __restrict__ qkv, float* __restrict__ ctx)
{
    extern __shared__ float sm[];
    float (*Qs)[PITCH] = (float(*)[PITCH])(sm);
    float (*Ks)[PITCH] = (float(*)[PITCH])(sm + 64 * PITCH);
    float (*Vs)[PITCH] = (float(*)[PITCH])(sm + 2 * 64 * PITCH);
    float (*Ps)[PITCH] = (float(*)[PITCH])(sm + 3 * 64 * PITCH);

    const int qi = blockIdx.x;
    const int bh = blockIdx.y;
    const int b  = bh >> 4;
    const int h  = bh & 15;

    const int tid = threadIdx.x;
    const int ty = tid >> 4;
    const int tx = tid & 15;
    const float scale = 0.125f;

    const float* base = qkv + (size_t)b * TT * QKV_N + h * HD;

    for (int idx = tid; idx < 64 * 64; idx += 256) {
        int r = idx >> 6, c = idx & 63;
        Qs[r][c] = base[(size_t)(qi * 64 + r) * QKV_N + c];
    }

    float m[4], l[4], acc[4][4];
#pragma unroll
    for (int a = 0; a < 4; a++) {
        m[a] = -INFINITY; l[a] = 0.f;
#pragma unroll
        for (int j = 0; j < 4; j++) acc[a][j] = 0.f;
    }

    for (int jt = 0; jt <= qi; jt++) {
        __syncthreads();
        for (int idx = tid; idx < 64 * 64; idx += 256) {
            int r = idx >> 6, c = idx & 63;
            size_t rowoff = (size_t)(jt * 64 + r) * QKV_N;
            Ks[r][c] = base[rowoff + DD + c];
            Vs[r][c] = base[rowoff + 2 * DD + c];
        }
        __syncthreads();

        float s[4][4];
#pragma unroll
        for (int a = 0; a < 4; a++)
#pragma unroll
            for (int j = 0; j < 4; j++) s[a][j] = 0.f;

        for (int d = 0; d < 64; d++) {
            float qv[4], kv[4];
#pragma unroll
            for (int a = 0; a < 4; a++) qv[a] = Qs[ty * 4 + a][d];
#pragma unroll
            for (int j = 0; j < 4; j++) kv[j] = Ks[tx * 4 + j][d];
#pragma unroll
            for (int a = 0; a < 4; a++)
#pragma unroll
                for (int j = 0; j < 4; j++)
                    s[a][j] += qv[a] * kv[j];
        }

#pragma unroll
        for (int a = 0; a < 4; a++)
#pragma unroll
            for (int j = 0; j < 4; j++) {
                s[a][j] *= scale;
                if (jt == qi && (tx * 4 + j) > (ty * 4 + a))
                    s[a][j] = -INFINITY;
            }

#pragma unroll
        for (int a = 0; a < 4; a++) {
            float rm = fmaxf(fmaxf(s[a][0], s[a][1]), fmaxf(s[a][2], s[a][3]));
#pragma unroll
            for (int off = 8; off >= 1; off >>= 1)
                rm = fmaxf(rm, __shfl_xor_sync(0xffffffffu, rm, off));

            float mn = fmaxf(m[a], rm);
            float alpha = expf(m[a] - mn);

            float rs = 0.f;
            float p[4];
#pragma unroll
            for (int j = 0; j < 4; j++) {
                p[j] = expf(s[a][j] - mn);
                rs += p[j];
            }
#pragma unroll
            for (int off = 8; off >= 1; off >>= 1)
                rs += __shfl_xor_sync(0xffffffffu, rs, off);

            l[a] = l[a] * alpha + rs;
            m[a] = mn;
#pragma unroll
            for (int j = 0; j < 4; j++) acc[a][j] *= alpha;

#pragma unroll
            for (int j = 0; j < 4; j++)
                Ps[ty * 4 + a][tx * 4 + j] = p[j];
        }
        __syncthreads();

        for (int k = 0; k < 64; k++) {
            float pv[4], vv[4];
#pragma unroll
            for (int a = 0; a < 4; a++) pv[a] = Ps[ty * 4 + a][k];
#pragma unroll
            for (int j = 0; j < 4; j++) vv[j] = Vs[k][tx * 4 + j];
#pragma unroll
            for (int a = 0; a < 4; a++)
#pragma unroll
                for (int j = 0; j < 4; j++)
                    acc[a][j] += pv[a] * vv[j];
        }
    }

#pragma unroll
    for (int a = 0; a < 4; a++) {
        float inv = 1.f / l[a];
        int trow = qi * 64 + ty * 4 + a;
        float4 o = make_float4(acc[a][0] * inv, acc[a][1] * inv,
                               acc[a][2] * inv, acc[a][3] * inv);
        *(float4*)&ctx[((size_t)(b * TT + trow)) * DD + h * HD + tx * 4] = o;
    }
}

// ---------------------------------------------------------------------------
// Launch
// ---------------------------------------------------------------------------
extern "C" void kernel_launch(void* const* d_in, const int* in_sizes, int n_in,
                              void* d_out, int out_size)
{
    const float* x     = (const float*)d_in[0];
    const float* w_qkv = (const float*)d_in[2];
    const float* w_out = (const float*)d_in[3];
    float* out = (float*)d_out;

    float *qkv_p, *ctx_p;
    __nv_bfloat16 *xh, *xl, *wqh, *wql, *woh, *wol, *ch, *cl;
    cudaGetSymbolAddress((void**)&qkv_p, g_qkv);
    cudaGetSymbolAddress((void**)&ctx_p, g_ctx);
    cudaGetSymbolAddress((void**)&xh, g_xh);
    cudaGetSymbolAddress((void**)&xl, g_xl);
    cudaGetSymbolAddress((void**)&wqh, g_wqh);
    cudaGetSymbolAddress((void**)&wql, g_wql);
    cudaGetSymbolAddress((void**)&woh, g_woh);
    cudaGetSymbolAddress((void**)&wol, g_wol);
    cudaGetSymbolAddress((void**)&ch, g_ch);
    cudaGetSymbolAddress((void**)&cl, g_cl);

    cudaFuncSetAttribute(attn64, cudaFuncAttributeMaxDynamicSharedMemorySize,
                         ATTN_SMEM);
    cudaFuncSetAttribute(gemm_mma, cudaFuncAttributeMaxDynamicSharedMemorySize,
                         GEMM_SMEM);

    // split/convert inputs
    split_rm<<<(ROWS * DD / 4 + 255) / 256, 256>>>((const float4*)x, xh, xl,
                                                   ROWS * DD / 4);
    split_tr<<<dim3(QKV_N / 32, DD / 32), dim3(32, 8)>>>(w_qkv, wqh, wql,
                                                         DD, QKV_N);
    split_tr<<<dim3(DD / 32, DD / 32), dim3(32, 8)>>>(w_out, woh, wol, DD, DD);

    // 1) QKV projection (mma.sync bf16 split-3)
    gemm_mma<<<dim3(QKV_N / 128, ROWS / 128), 256, GEMM_SMEM>>>(
        xh, xl, wqh, wql, qkv_p, ROWS, QKV_N, DD);

    // 2) fused causal attention (fp32)
    attn64<<<dim3(TT / 64, BB * HH), 256, ATTN_SMEM>>>(qkv_p, ctx_p);

    // split ctx for second GEMM
    split_rm<<<(ROWS * DD / 4 + 255) / 256, 256>>>((const float4*)ctx_p, ch, cl,
                                                   ROWS * DD / 4);

    // 3) output projection (mma.sync bf16 split-3)
    gemm_mma<<<dim3(DD / 128, ROWS / 128), 256, GEMM_SMEM>>>(
        ch, cl, woh, wol, out, ROWS, DD, DD);
}

// round 7
// speedup vs baseline: 3.3831x; 2.1357x over previous
#include <cuda_runtime.h>
#include <cuda_bf16.h>
#include <cuda_fp16.h>
#include <math.h>
#include <stdint.h>

// Problem constants
#define BB 4
#define TT 1024
#define DD 1024
#define HH 16
#define HD 64
#define ROWS (BB * TT)        // 4096
#define QKV_N (3 * DD)        // 3072

// ---------------------------------------------------------------------------
// Scratch (allocation-free: __device__ globals)
// ---------------------------------------------------------------------------
__device__ __half g_qkvh[ROWS * QKV_N];           // qkv fp16 [4096, 3072]
__device__ __nv_bfloat16 g_xh[ROWS * DD];         // x hi/lo  [4096,1024]
__device__ __nv_bfloat16 g_xl[ROWS * DD];
__device__ __nv_bfloat16 g_wqh[QKV_N * DD];       // w_qkv^T hi/lo [3072,1024]
__device__ __nv_bfloat16 g_wql[QKV_N * DD];
__device__ __nv_bfloat16 g_woh[DD * DD];          // w_out^T hi/lo [1024,1024]
__device__ __nv_bfloat16 g_wol[DD * DD];
__device__ __nv_bfloat16 g_ch[ROWS * DD];         // ctx hi/lo [4096,1024]
__device__ __nv_bfloat16 g_cl[ROWS * DD];

// ---------------------------------------------------------------------------
// Baseline-PTX helpers (cp.async, ldmatrix, HMMA)
// ---------------------------------------------------------------------------
__device__ __forceinline__ uint32_t smem_u32(const void* p) {
    uint32_t a;
    asm("{ .reg .u64 t; cvta.to.shared.u64 t, %1; cvt.u32.u64 %0, t; }"
        : "=r"(a) : "l"(p));
    return a;
}
__device__ __forceinline__ void cp_async16(uint32_t dst, const void* src) {
    asm volatile("cp.async.cg.shared.global [%0], [%1], 16;\n"
                 :: "r"(dst), "l"(src));
}
#define CP_COMMIT() asm volatile("cp.async.commit_group;" ::: "memory")
#define CP_WAIT(n)  asm volatile("cp.async.wait_group %0;" :: "n"(n) : "memory")

__device__ __forceinline__ void ldsm_x4(uint32_t* r, uint32_t addr) {
    asm volatile("ldmatrix.sync.aligned.m8n8.x4.shared.b16 {%0,%1,%2,%3}, [%4];"
                 : "=r"(r[0]), "=r"(r[1]), "=r"(r[2]), "=r"(r[3]) : "r"(addr));
}
__device__ __forceinline__ void ldsm_x4_t(uint32_t* r, uint32_t addr) {
    asm volatile("ldmatrix.sync.aligned.m8n8.x4.trans.shared.b16 {%0,%1,%2,%3}, [%4];"
                 : "=r"(r[0]), "=r"(r[1]), "=r"(r[2]), "=r"(r[3]) : "r"(addr));
}
__device__ __forceinline__ void mma_bf(float* d, const uint32_t* a,
                                       const uint32_t* b) {
    asm volatile(
        "mma.sync.aligned.m16n8k16.row.col.f32.bf16.bf16.f32 "
        "{%0,%1,%2,%3}, {%4,%5,%6,%7}, {%8,%9}, {%0,%1,%2,%3};"
        : "+f"(d[0]), "+f"(d[1]), "+f"(d[2]), "+f"(d[3])
        : "r"(a[0]), "r"(a[1]), "r"(a[2]), "r"(a[3]), "r"(b[0]), "r"(b[1]));
}
__device__ __forceinline__ void mma_hf(float* d, const uint32_t* a,
                                       const uint32_t* b) {
    asm volatile(
        "mma.sync.aligned.m16n8k16.row.col.f32.f16.f16.f32 "
        "{%0,%1,%2,%3}, {%4,%5,%6,%7}, {%8,%9}, {%0,%1,%2,%3};"
        : "+f"(d[0]), "+f"(d[1]), "+f"(d[2]), "+f"(d[3])
        : "r"(a[0]), "r"(a[1]), "r"(a[2]), "r"(a[3]), "r"(b[0]), "r"(b[1]));
}
__device__ __forceinline__ float ex2f(float x) {
    float r;
    asm("ex2.approx.f32 %0, %1;" : "=f"(r) : "f"(x));
    return r;
}
// fp32 pair -> (bf16x2 hi, bf16x2 lo)
__device__ __forceinline__ void split2b(float a, float b,
                                        uint32_t& hi, uint32_t& lo) {
    __nv_bfloat162 h2 = __floats2bfloat162_rn(a, b);
    uint32_t hu = *(uint32_t*)&h2;
    float ha = __uint_as_float(hu << 16);
    float hb = __uint_as_float(hu & 0xffff0000u);
    __nv_bfloat162 l2 = __floats2bfloat162_rn(a - ha, b - hb);
    hi = hu;
    lo = *(uint32_t*)&l2;
}
__device__ __forceinline__ uint32_t packh2(float a, float b) {
    __half2 h = __floats2half2_rn(a, b);
    return *(uint32_t*)&h;
}
// SW128 swizzle for 128-byte rows: conflict-free cp.async + ldmatrix
__device__ __forceinline__ uint32_t sw128(uint32_t r, uint32_t c) {
    return r * 128u + (c ^ ((r & 7u) * 16u));
}

// ---------------------------------------------------------------------------
// split kernels: fp32 -> (hi bf16, lo bf16)
// ---------------------------------------------------------------------------
__global__ void __launch_bounds__(256) split_rm(
    const float4* __restrict__ src, __nv_bfloat16* __restrict__ hi,
    __nv_bfloat16* __restrict__ lo, int n4)
{
    int i = blockIdx.x * blockDim.x + threadIdx.x;
    if (i >= n4) return;
    float4 v = src[i];
    uint32_t h0, l0, h1, l1;
    split2b(v.x, v.y, h0, l0);
    split2b(v.z, v.w, h1, l1);
    uint32_t* hp = reinterpret_cast<uint32_t*>(hi) + 2 * i;
    uint32_t* lp = reinterpret_cast<uint32_t*>(lo) + 2 * i;
    hp[0] = h0; hp[1] = h1;
    lp[0] = l0; lp[1] = l1;
}

// transpose + split: src [K,N] fp32 -> dst [N,K] hi/lo bf16
__global__ void __launch_bounds__(256) split_tr(
    const float* __restrict__ src, __nv_bfloat16* __restrict__ hi,
    __nv_bfloat16* __restrict__ lo, int K, int N)
{
    __shared__ float t[32][33];
    int k0 = blockIdx.y * 32, n0 = blockIdx.x * 32;
    int tx = threadIdx.x, ty = threadIdx.y;      // (32, 8)
#pragma unroll
    for (int i = 0; i < 32; i += 8)
        t[ty + i][tx] = src[(size_t)(k0 + ty + i) * N + n0 + tx];
    __syncthreads();
#pragma unroll
    for (int i = 0; i < 32; i += 8) {
        float v = t[tx][ty + i];
        __nv_bfloat16 h = __float2bfloat16(v);
        __nv_bfloat16 l = __float2bfloat16(v - __bfloat162float(h));
        size_t o = (size_t)(n0 + ty + i) * K + k0 + tx;
        hi[o] = h;
        lo[o] = l;
    }
}

// ---------------------------------------------------------------------------
// mma.sync split-bf16 GEMM: C[M,N] = A[M,K] @ Bt[N,K]^T
// OUT=0: fp32 C.  OUT=1: fp16 Ch.
// CTA 128x128, BK=32, 8 warps, 2-stage cp.async (2 CTAs/SM).
// ---------------------------------------------------------------------------
#define APITCH 80
#define TILE_BYTES (128 * APITCH)                 // 10240
#define STAGE_BYTES (4 * TILE_BYTES)              // 40960
#define GEMM_SMEM (2 * STAGE_BYTES)               // 81920

template <int OUT>
__global__ void __launch_bounds__(256, 2) gemm_mma(
    const __nv_bfloat16* __restrict__ Ah, const __nv_bfloat16* __restrict__ Al,
    const __nv_bfloat16* __restrict__ Bh, const __nv_bfloat16* __restrict__ Bl,
    float* __restrict__ C, __half* __restrict__ Ch, int M, int N, int K)
{
    extern __shared__ char dynsm[];
    const uint32_t sm0 = smem_u32(dynsm);

    const int tid  = threadIdx.x;
    const int wid  = tid >> 5;
    const int lane = tid & 31;
    const int m0 = blockIdx.y * 128;
    const int n0 = blockIdx.x * 128;

    const int warp_m = (wid & 3) * 32;
    const int warp_n = (wid >> 2) * 64;

    const int nch = K / 32;

    auto load_stage = [&](int kc, int stage) {
        const uint32_t sb = sm0 + stage * STAGE_BYTES;
        const int ke = kc * 32;
#pragma unroll
        for (int i = 0; i < 8; i++) {
            int t = tid + i * 256;
            int tile = t >> 9;
            int r = (t >> 2) & 127;
            int j = t & 3;
            uint32_t dst = sb + tile * TILE_BYTES + r * APITCH + j * 16;
            size_t goff;
            const __nv_bfloat16* src;
            if (tile == 0)      { src = Ah; goff = (size_t)(m0 + r) * K + ke + j * 8; }
            else if (tile == 1) { src = Al; goff = (size_t)(m0 + r) * K + ke + j * 8; }
            else if (tile == 2) { src = Bh; goff = (size_t)(n0 + r) * K + ke + j * 8; }
            else                { src = Bl; goff = (size_t)(n0 + r) * K + ke + j * 8; }
            cp_async16(dst, src + goff);
        }
        CP_COMMIT();
    };

    const uint32_t a_row = warp_m + (lane & 15);
    const uint32_t a_kof = (uint32_t)(lane >> 4) * 16;
    const uint32_t b_row = warp_n + (lane & 7) + ((lane >> 4) << 3);
    const uint32_t b_kof = (uint32_t)((lane >> 3) & 1) * 16;

    float acc[2][8][4];
#pragma unroll
    for (int mt = 0; mt < 2; mt++)
#pragma unroll
        for (int nt = 0; nt < 8; nt++)
#pragma unroll
            for (int e = 0; e < 4; e++) acc[mt][nt][e] = 0.f;

    load_stage(0, 0);
    load_stage(1, 1);

    for (int c = 0; c < nch; c++) {
        if (c + 1 < nch) { CP_WAIT(1); } else { CP_WAIT(0); }
        __syncthreads();

        const uint32_t sb = sm0 + (c & 1) * STAGE_BYTES;
        const uint32_t aH = sb;
        const uint32_t aL = sb + TILE_BYTES;
        const uint32_t bH = sb + 2 * TILE_BYTES;
        const uint32_t bL = sb + 3 * TILE_BYTES;

#pragma unroll
        for (int ks = 0; ks < 2; ks++) {
            const uint32_t ks32 = ks * 32;
            uint32_t ah[2][4], al[2][4];
#pragma unroll
            for (int mt = 0; mt < 2; mt++) {
                uint32_t off = (a_row + mt * 16) * APITCH + ks32 + a_kof;
                ldsm_x4(ah[mt], aH + off);
                ldsm_x4(al[mt], aL + off);
            }
            uint32_t bh[8][2], bl[8][2];
#pragma unroll
            for (int p = 0; p < 4; p++) {
                uint32_t off = (b_row + p * 16) * APITCH + ks32 + b_kof;
                uint32_t q[4];
                ldsm_x4(q, bH + off);
                bh[2 * p][0] = q[0]; bh[2 * p][1] = q[1];
                bh[2 * p + 1][0] = q[2]; bh[2 * p + 1][1] = q[3];
                ldsm_x4(q, bL + off);
                bl[2 * p][0] = q[0]; bl[2 * p][1] = q[1];
                bl[2 * p + 1][0] = q[2]; bl[2 * p + 1][1] = q[3];
            }
#pragma unroll
            for (int mt = 0; mt < 2; mt++)
#pragma unroll
                for (int nt = 0; nt < 8; nt++) {
                    mma_bf(acc[mt][nt], ah[mt], bh[nt]);
                    mma_bf(acc[mt][nt], ah[mt], bl[nt]);
                    mma_bf(acc[mt][nt], al[mt], bh[nt]);
                }
        }
        __syncthreads();
        if (c + 2 < nch) load_stage(c + 2, c & 1);
    }

    const int erow = m0 + warp_m + (lane >> 2);
    const int ecol = n0 + warp_n + (lane & 3) * 2;
#pragma unroll
    for (int mt = 0; mt < 2; mt++) {
#pragma unroll
        for (int nt = 0; nt < 8; nt++) {
            size_t o0 = (size_t)(erow + mt * 16) * N + ecol + nt * 8;
            size_t o1 = (size_t)(erow + mt * 16 + 8) * N + ecol + nt * 8;
            if (OUT == 0) {
                *(float2*)(C + o0) = make_float2(acc[mt][nt][0], acc[mt][nt][1]);
                *(float2*)(C + o1) = make_float2(acc[mt][nt][2], acc[mt][nt][3]);
            } else {
                *(uint32_t*)(Ch + o0) = packh2(acc[mt][nt][0], acc[mt][nt][1]);
                *(uint32_t*)(Ch + o1) = packh2(acc[mt][nt][2], acc[mt][nt][3]);
            }
        }
    }
}

// ---------------------------------------------------------------------------
// Tensor-core flash attention, fp16 single-pass.
// CTA = (q-block 128, one b,h); 4 warps, warp = 32 q rows; KV tile 64.
// SMEM rows are 128 bytes (HD=64 fp16) with SW128 swizzle.
// Output: ctx split to bf16 hi/lo [4096,1024].
// ---------------------------------------------------------------------------
#define QTILE_B (128 * 128)                       // 16384
#define KVSTAGE_B (2 * 64 * 128)                  // 16384 (K + V)
#define ATT_SMEM (QTILE_B + 2 * KVSTAGE_B)        // 49152

__global__ void __launch_bounds__(128) attn_f16(
    const __half* __restrict__ qkv,
    __nv_bfloat16* __restrict__ chp, __nv_bfloat16* __restrict__ clp)
{
    extern __shared__ char smbuf[];
    const uint32_t smQ = smem_u32(smbuf);

    const int tid  = threadIdx.x;
    const int wid  = tid >> 5;
    const int lane = tid & 31;
    const int qb = gridDim.x - 1 - blockIdx.x;   // heavy blocks first
    const int b  = blockIdx.y >> 4;
    const int h  = blockIdx.y & 15;
    const int warp_m = wid * 32;
    const int nkv = 2 * qb + 2;
    const int qrow0 = qb * 128;                  // q row base (within T)

    const __half* qbase = qkv + ((size_t)b * TT + qrow0) * QKV_N + h * HD;

    // Q tile load [128 x 64 fp16], swizzled 128B rows
#pragma unroll
    for (int i = 0; i < 8; i++) {
        int t = tid + i * 128;
        int r = t >> 3, j = t & 7;
        cp_async16(smQ + sw128(r, j * 16), qbase + (size_t)r * QKV_N + j * 8);
    }
    CP_COMMIT();

    auto load_kv = [&](int jt, int st) {
        const __half* kb = qkv + ((size_t)b * TT + jt * 64) * QKV_N + h * HD;
        const uint32_t sb = smQ + QTILE_B + st * KVSTAGE_B;
#pragma unroll
        for (int i = 0; i < 8; i++) {
            int t = tid + i * 128;
            int tile = t >> 9;                    // 0 = K, 1 = V
            int r = (t >> 3) & 63, j = t & 7;
            cp_async16(sb + tile * (64 * 128) + sw128(r, j * 16),
                       kb + (size_t)r * QKV_N + (tile ? 2048 : 1024) + j * 8);
        }
        CP_COMMIT();
    };

    load_kv(0, 0);
    load_kv(1, 1);

    CP_WAIT(2);              // Q group done
    __syncthreads();

    // preload Q fragments (invariant across kv tiles)
    uint32_t qf[2][4][4];
#pragma unroll
    for (int mt = 0; mt < 2; mt++)
#pragma unroll
        for (int ks = 0; ks < 4; ks++)
            ldsm_x4(qf[mt][ks],
                    smQ + sw128(warp_m + mt * 16 + (lane & 15),
                                ks * 32 + (lane >> 4) * 16));

    float acc[2][8][4];
    float mrow[2][2], lrow[2][2];
#pragma unroll
    for (int mt = 0; mt < 2; mt++) {
#pragma unroll
        for (int hf = 0; hf < 2; hf++) { mrow[mt][hf] = -1e30f; lrow[mt][hf] = 0.f; }
#pragma unroll
        for (int nt = 0; nt < 8; nt++)
#pragma unroll
            for (int e = 0; e < 4; e++) acc[mt][nt][e] = 0.f;
    }

    const float SC = 0.18033688f;                // 0.125 * log2(e)
    const int row_lo = lane >> 2;                // row within m16 (low half)

    for (int c = 0; c < nkv; c++) {
        if (c + 1 < nkv) { CP_WAIT(1); } else { CP_WAIT(0); }
        __syncthreads();

        const uint32_t smK = smQ + QTILE_B + (c & 1) * KVSTAGE_B;
        const uint32_t smV = smK + 64 * 128;
        const bool active = (c * 64 <= qrow0 + warp_m + 31);

        if (active) {
            // ---- S = Q K^T ----
            float S[2][8][4];
#pragma unroll
            for (int mt = 0; mt < 2; mt++)
#pragma unroll
                for (int nt = 0; nt < 8; nt++)
#pragma unroll
                    for (int e = 0; e < 4; e++) S[mt][nt][e] = 0.f;

#pragma unroll
            for (int ks = 0; ks < 4; ks++) {
                uint32_t bk[8][2];
#pragma unroll
                for (int p = 0; p < 4; p++) {
                    uint32_t q[4];
                    ldsm_x4(q, smK + sw128(p * 16 + (lane & 7) + ((lane >> 4) << 3),
                                           ks * 32 + ((lane >> 3) & 1) * 16));
                    bk[2 * p][0] = q[0]; bk[2 * p][1] = q[1];
                    bk[2 * p + 1][0] = q[2]; bk[2 * p + 1][1] = q[3];
                }
#pragma unroll
                for (int mt = 0; mt < 2; mt++)
#pragma unroll
                    for (int nt = 0; nt < 8; nt++)
                        mma_hf(S[mt][nt], qf[mt][ks], bk[nt]);
            }

            // ---- scale + causal mask (t-domain: *SC) ----
#pragma unroll
            for (int mt = 0; mt < 2; mt++) {
                const int rbase = qrow0 + warp_m + mt * 16 + row_lo;
                const bool nm = (c * 64 + 63 > qrow0 + warp_m + mt * 16);
#pragma unroll
                for (int nt = 0; nt < 8; nt++)
#pragma unroll
                    for (int e = 0; e < 4; e++) {
                        float t = S[mt][nt][e] * SC;
                        if (nm) {
                            int col = c * 64 + nt * 8 + (lane & 3) * 2 + (e & 1);
                            int row = rbase + (e >> 1) * 8;
                            if (col > row) t = -1e30f;
                        }
                        S[mt][nt][e] = t;
                    }
            }

            // ---- online softmax ----
#pragma unroll
            for (int mt = 0; mt < 2; mt++) {
#pragma unroll
                for (int hf = 0; hf < 2; hf++) {
                    float rm = -1e30f;
#pragma unroll
                    for (int nt = 0; nt < 8; nt++) {
                        rm = fmaxf(rm, S[mt][nt][hf * 2]);
                        rm = fmaxf(rm, S[mt][nt][hf * 2 + 1]);
                    }
                    rm = fmaxf(rm, __shfl_xor_sync(0xffffffffu, rm, 1));
                    rm = fmaxf(rm, __shfl_xor_sync(0xffffffffu, rm, 2));

                    float mn = fmaxf(mrow[mt][hf], rm);
                    float alpha = ex2f(mrow[mt][hf] - mn);
                    mrow[mt][hf] = mn;

                    float rs = 0.f;
#pragma unroll
                    for (int nt = 0; nt < 8; nt++) {
                        float p0 = ex2f(S[mt][nt][hf * 2] - mn);
                        float p1 = ex2f(S[mt][nt][hf * 2 + 1] - mn);
                        S[mt][nt][hf * 2] = p0;
                        S[mt][nt][hf * 2 + 1] = p1;
                        rs += p0 + p1;
                    }
                    rs += __shfl_xor_sync(0xffffffffu, rs, 1);
                    rs += __shfl_xor_sync(0xffffffffu, rs, 2);
                    lrow[mt][hf] = lrow[mt][hf] * alpha + rs;

#pragma unroll
                    for (int nt = 0; nt < 8; nt++) {
                        acc[mt][nt][hf * 2] *= alpha;
                        acc[mt][nt][hf * 2 + 1] *= alpha;
                    }
                }
            }

            // ---- pack P -> fp16 A-fragments ----
            uint32_t pa[2][4][4];
#pragma unroll
            for (int mt = 0; mt < 2; mt++)
#pragma unroll
                for (int kk = 0; kk < 4; kk++) {
                    pa[mt][kk][0] = packh2(S[mt][2 * kk][0], S[mt][2 * kk][1]);
                    pa[mt][kk][1] = packh2(S[mt][2 * kk][2], S[mt][2 * kk][3]);
                    pa[mt][kk][2] = packh2(S[mt][2 * kk + 1][0], S[mt][2 * kk + 1][1]);
                    pa[mt][kk][3] = packh2(S[mt][2 * kk + 1][2], S[mt][2 * kk + 1][3]);
                }

            // ---- O += P V ----
#pragma unroll
            for (int ks = 0; ks < 4; ks++) {
                uint32_t bv[8][2];
#pragma unroll
                for (int nb = 0; nb < 4; nb++) {
                    uint32_t q[4];
                    ldsm_x4_t(q, smV + sw128(ks * 16 + (lane & 15),
                                             nb * 32 + ((lane >> 4) << 4)));
                    bv[2 * nb][0] = q[0]; bv[2 * nb][1] = q[1];
                    bv[2 * nb + 1][0] = q[2]; bv[2 * nb + 1][1] = q[3];
                }
#pragma unroll
                for (int mt = 0; mt < 2; mt++)
#pragma unroll
                    for (int nt = 0; nt < 8; nt++)
                        mma_hf(acc[mt][nt], pa[mt][ks], bv[nt]);
            }
        }
        __syncthreads();
        if (c + 2 < nkv) load_kv(c + 2, c & 1);
    }

    // ---- epilogue: normalize, split to bf16 hi/lo, store ----
#pragma unroll
    for (int mt = 0; mt < 2; mt++) {
#pragma unroll
        for (int hf = 0; hf < 2; hf++) {
            float inv = 1.f / lrow[mt][hf];
            int token = qrow0 + warp_m + mt * 16 + row_lo + hf * 8;
            size_t rbase = ((size_t)b * TT + token) * DD + h * HD;
#pragma unroll
            for (int nt = 0; nt < 8; nt++) {
                int col = nt * 8 + (lane & 3) * 2;
                float o0 = acc[mt][nt][hf * 2] * inv;
                float o1 = acc[mt][nt][hf * 2 + 1] * inv;
                uint32_t hi, lo;
                split2b(o0, o1, hi, lo);
                *(uint32_t*)(chp + rbase + col) = hi;
                *(uint32_t*)(clp + rbase + col) = lo;
            }
        }
    }
}

// ---------------------------------------------------------------------------
// Launch
// ---------------------------------------------------------------------------
extern "C" void kernel_launch(void* const* d_in, const int* in_sizes, int n_in,
                              void* d_out, int out_size)
{
    const float* x     = (const float*)d_in[0];
    const float* w_qkv = (const float*)d_in[2];
    const float* w_out = (const float*)d_in[3];
    float* out = (float*)d_out;

    __half* qkvh;
    __nv_bfloat16 *xh, *xl, *wqh, *wql, *woh, *wol, *ch, *cl;
    cudaGetSymbolAddress((void**)&qkvh, g_qkvh);
    cudaGetSymbolAddress((void**)&xh, g_xh);
    cudaGetSymbolAddress((void**)&xl, g_xl);
    cudaGetSymbolAddress((void**)&wqh, g_wqh);
    cudaGetSymbolAddress((void**)&wql, g_wql);
    cudaGetSymbolAddress((void**)&woh, g_woh);
    cudaGetSymbolAddress((void**)&wol, g_wol);
    cudaGetSymbolAddress((void**)&ch, g_ch);
    cudaGetSymbolAddress((void**)&cl, g_cl);

    cudaFuncSetAttribute(gemm_mma<0>, cudaFuncAttributeMaxDynamicSharedMemorySize,
                         GEMM_SMEM);
    cudaFuncSetAttribute(gemm_mma<1>, cudaFuncAttributeMaxDynamicSharedMemorySize,
                         GEMM_SMEM);
    cudaFuncSetAttribute(attn_f16, cudaFuncAttributeMaxDynamicSharedMemorySize,
                         ATT_SMEM);

    // split/convert inputs
    split_rm<<<(ROWS * DD / 4 + 255) / 256, 256>>>((const float4*)x, xh, xl,
                                                   ROWS * DD / 4);
    split_tr<<<dim3(QKV_N / 32, DD / 32), dim3(32, 8)>>>(w_qkv, wqh, wql,
                                                         DD, QKV_N);
    split_tr<<<dim3(DD / 32, DD / 32), dim3(32, 8)>>>(w_out, woh, wol, DD, DD);

    // 1) QKV projection -> fp16 qkv
    gemm_mma<1><<<dim3(QKV_N / 128, ROWS / 128), 256, GEMM_SMEM>>>(
        xh, xl, wqh, wql, nullptr, qkvh, ROWS, QKV_N, DD);

    // 2) fused causal attention (fp16 tensor cores) -> bf16 hi/lo ctx
    attn_f16<<<dim3(TT / 128, BB * HH), 128, ATT_SMEM>>>(qkvh, ch, cl);

    // 3) output projection -> fp32 out
    gemm_mma<0><<<dim3(DD / 128, ROWS / 128), 256, GEMM_SMEM>>>(
        ch, cl, woh, wol, out, nullptr, ROWS, DD, DD);
}

// round 8
// speedup vs baseline: 5.7811x; 1.7088x over previous
#include <cuda_runtime.h>
#include <cuda_bf16.h>
#include <cuda_fp16.h>
#include <math.h>
#include <stdint.h>

// Problem constants
#define BB 4
#define TT 1024
#define DD 1024
#define HH 16
#define HD 64
#define ROWS (BB * TT)        // 4096
#define QKV_N (3 * DD)        // 3072

// ---------------------------------------------------------------------------
// Scratch (allocation-free: __device__ globals)
// ---------------------------------------------------------------------------
__device__ __half g_qkvh[ROWS * QKV_N];           // qkv fp16 [4096, 3072]
__device__ __half g_xf[ROWS * DD];                // x fp16 [4096,1024]
__device__ __half g_wqf[QKV_N * DD];              // w_qkv^T fp16 [3072,1024]
__device__ __nv_bfloat16 g_woh[DD * DD];          // w_out^T hi/lo [1024,1024]
__device__ __nv_bfloat16 g_wol[DD * DD];
__device__ __nv_bfloat16 g_ch[ROWS * DD];         // ctx hi/lo [4096,1024]
__device__ __nv_bfloat16 g_cl[ROWS * DD];

// ---------------------------------------------------------------------------
// Baseline-PTX helpers (cp.async, ldmatrix, HMMA)
// ---------------------------------------------------------------------------
__device__ __forceinline__ uint32_t smem_u32(const void* p) {
    uint32_t a;
    asm("{ .reg .u64 t; cvta.to.shared.u64 t, %1; cvt.u32.u64 %0, t; }"
        : "=r"(a) : "l"(p));
    return a;
}
__device__ __forceinline__ void cp_async16(uint32_t dst, const void* src) {
    asm volatile("cp.async.cg.shared.global [%0], [%1], 16;\n"
                 :: "r"(dst), "l"(src));
}
#define CP_COMMIT() asm volatile("cp.async.commit_group;" ::: "memory")
#define CP_WAIT(n)  asm volatile("cp.async.wait_group %0;" :: "n"(n) : "memory")

__device__ __forceinline__ void ldsm_x4(uint32_t* r, uint32_t addr) {
    asm volatile("ldmatrix.sync.aligned.m8n8.x4.shared.b16 {%0,%1,%2,%3}, [%4];"
                 : "=r"(r[0]), "=r"(r[1]), "=r"(r[2]), "=r"(r[3]) : "r"(addr));
}
__device__ __forceinline__ void ldsm_x4_t(uint32_t* r, uint32_t addr) {
    asm volatile("ldmatrix.sync.aligned.m8n8.x4.trans.shared.b16 {%0,%1,%2,%3}, [%4];"
                 : "=r"(r[0]), "=r"(r[1]), "=r"(r[2]), "=r"(r[3]) : "r"(addr));
}
__device__ __forceinline__ void mma_bf(float* d, const uint32_t* a,
                                       const uint32_t* b) {
    asm volatile(
        "mma.sync.aligned.m16n8k16.row.col.f32.bf16.bf16.f32 "
        "{%0,%1,%2,%3}, {%4,%5,%6,%7}, {%8,%9}, {%0,%1,%2,%3};"
        : "+f"(d[0]), "+f"(d[1]), "+f"(d[2]), "+f"(d[3])
        : "r"(a[0]), "r"(a[1]), "r"(a[2]), "r"(a[3]), "r"(b[0]), "r"(b[1]));
}
__device__ __forceinline__ void mma_hf(float* d, const uint32_t* a,
                                       const uint32_t* b) {
    asm volatile(
        "mma.sync.aligned.m16n8k16.row.col.f32.f16.f16.f32 "
        "{%0,%1,%2,%3}, {%4,%5,%6,%7}, {%8,%9}, {%0,%1,%2,%3};"
        : "+f"(d[0]), "+f"(d[1]), "+f"(d[2]), "+f"(d[3])
        : "r"(a[0]), "r"(a[1]), "r"(a[2]), "r"(a[3]), "r"(b[0]), "r"(b[1]));
}
__device__ __forceinline__ float ex2f(float x) {
    float r;
    asm("ex2.approx.f32 %0, %1;" : "=f"(r) : "f"(x));
    return r;
}
// fp32 pair -> (bf16x2 hi, bf16x2 lo)
__device__ __forceinline__ void split2b(float a, float b,
                                        uint32_t& hi, uint32_t& lo) {
    __nv_bfloat162 h2 = __floats2bfloat162_rn(a, b);
    uint32_t hu = *(uint32_t*)&h2;
    float ha = __uint_as_float(hu << 16);
    float hb = __uint_as_float(hu & 0xffff0000u);
    __nv_bfloat162 l2 = __floats2bfloat162_rn(a - ha, b - hb);
    hi = hu;
    lo = *(uint32_t*)&l2;
}
__device__ __forceinline__ uint32_t packh2(float a, float b) {
    __half2 h = __floats2half2_rn(a, b);
    return *(uint32_t*)&h;
}
// SW128 swizzle for 128-byte rows: conflict-free cp.async + ldmatrix
__device__ __forceinline__ uint32_t sw128(uint32_t r, uint32_t c) {
    return r * 128u + (c ^ ((r & 7u) * 16u));
}

// ---------------------------------------------------------------------------
// convert kernels
// ---------------------------------------------------------------------------
// fp32 row-major -> fp16 row-major
__global__ void __launch_bounds__(256) conv_rm(
    const float4* __restrict__ src, __half* __restrict__ dst, int n4)
{
    int i = blockIdx.x * blockDim.x + threadIdx.x;
    if (i >= n4) return;
    float4 v = src[i];
    uint32_t* dp = reinterpret_cast<uint32_t*>(dst) + 2 * i;
    dp[0] = packh2(v.x, v.y);
    dp[1] = packh2(v.z, v.w);
}

// transpose: src [K,N] fp32 -> dst [N,K] fp16
__global__ void __launch_bounds__(256) conv_tr(
    const float* __restrict__ src, __half* __restrict__ dst, int K, int N)
{
    __shared__ float t[32][33];
    int k0 = blockIdx.y * 32, n0 = blockIdx.x * 32;
    int tx = threadIdx.x, ty = threadIdx.y;      // (32, 8)
#pragma unroll
    for (int i = 0; i < 32; i += 8)
        t[ty + i][tx] = src[(size_t)(k0 + ty + i) * N + n0 + tx];
    __syncthreads();
#pragma unroll
    for (int i = 0; i < 32; i += 8)
        dst[(size_t)(n0 + ty + i) * K + k0 + tx] = __float2half(t[tx][ty + i]);
}

// transpose + split: src [K,N] fp32 -> dst [N,K] hi/lo bf16
__global__ void __launch_bounds__(256) split_tr(
    const float* __restrict__ src, __nv_bfloat16* __restrict__ hi,
    __nv_bfloat16* __restrict__ lo, int K, int N)
{
    __shared__ float t[32][33];
    int k0 = blockIdx.y * 32, n0 = blockIdx.x * 32;
    int tx = threadIdx.x, ty = threadIdx.y;      // (32, 8)
#pragma unroll
    for (int i = 0; i < 32; i += 8)
        t[ty + i][tx] = src[(size_t)(k0 + ty + i) * N + n0 + tx];
    __syncthreads();
#pragma unroll
    for (int i = 0; i < 32; i += 8) {
        float v = t[tx][ty + i];
        __nv_bfloat16 h = __float2bfloat16(v);
        __nv_bfloat16 l = __float2bfloat16(v - __bfloat162float(h));
        size_t o = (size_t)(n0 + ty + i) * K + k0 + tx;
        hi[o] = h;
        lo[o] = l;
    }
}

// ---------------------------------------------------------------------------
// Single-fp16 GEMM: Ch[M,N] = A[M,K] @ Bt[N,K]^T   (fp16 out)
// CTA 128x128, BK=64, 8 warps (warp 32x64), 2-stage cp.async, SW128 smem.
// ---------------------------------------------------------------------------
#define HTILE_B (128 * 128)                       // 16384 (128 rows x 128B)
#define HSTAGE_B (2 * HTILE_B)                    // 32768 (A + B)
#define GEMMH_SMEM (2 * HSTAGE_B)                 // 65536

__global__ void __launch_bounds__(256, 2) gemm_hf(
    const __half* __restrict__ A, const __half* __restrict__ Bt,
    __half* __restrict__ Ch, int M, int N, int K)
{
    extern __shared__ char dynsm[];
    const uint32_t sm0 = smem_u32(dynsm);

    const int tid  = threadIdx.x;
    const int wid  = tid >> 5;
    const int lane = tid & 31;
    const int m0 = blockIdx.y * 128;
    const int n0 = blockIdx.x * 128;

    const int warp_m = (wid & 3) * 32;
    const int warp_n = (wid >> 2) * 64;

    const int nch = K / 64;

    auto load_stage = [&](int kc, int stage) {
        const uint32_t sb = sm0 + stage * HSTAGE_B;
        const int ke = kc * 64;
#pragma unroll
        for (int i = 0; i < 8; i++) {
            int t = tid + i * 256;
            int tile = t >> 10;                   // 0 = A, 1 = B
            int r = (t >> 3) & 127;
            int j = t & 7;
            uint32_t dst = sb + tile * HTILE_B + sw128(r, j * 16);
            const __half* src = tile ? (Bt + (size_t)(n0 + r) * K + ke + j * 8)
                                     : (A  + (size_t)(m0 + r) * K + ke + j * 8);
            cp_async16(dst, src);
        }
        CP_COMMIT();
    };

    const uint32_t a_row = warp_m + (lane & 15);
    const uint32_t a_kof = (uint32_t)(lane >> 4) * 16;
    const uint32_t b_row = warp_n + (lane & 7) + ((lane >> 4) << 3);
    const uint32_t b_kof = (uint32_t)((lane >> 3) & 1) * 16;

    float acc[2][8][4];
#pragma unroll
    for (int mt = 0; mt < 2; mt++)
#pragma unroll
        for (int nt = 0; nt < 8; nt++)
#pragma unroll
            for (int e = 0; e < 4; e++) acc[mt][nt][e] = 0.f;

    load_stage(0, 0);
    load_stage(1, 1);

    for (int c = 0; c < nch; c++) {
        if (c + 1 < nch) { CP_WAIT(1); } else { CP_WAIT(0); }
        __syncthreads();

        const uint32_t sA = sm0 + (c & 1) * HSTAGE_B;
        const uint32_t sB = sA + HTILE_B;

#pragma unroll
        for (int ks = 0; ks < 4; ks++) {
            const uint32_t k32 = ks * 32;         // byte offset of k-step
            uint32_t af[2][4];
#pragma unroll
            for (int mt = 0; mt < 2; mt++)
                ldsm_x4(af[mt], sA + sw128(a_row + mt * 16, k32 + a_kof));
            uint32_t bf[8][2];
#pragma unroll
            for (int p = 0; p < 4; p++) {
                uint32_t q[4];
                ldsm_x4(q, sB + sw128(b_row + p * 16, k32 + b_kof));
                bf[2 * p][0] = q[0]; bf[2 * p][1] = q[1];
                bf[2 * p + 1][0] = q[2]; bf[2 * p + 1][1] = q[3];
            }
#pragma unroll
            for (int mt = 0; mt < 2; mt++)
#pragma unroll
                for (int nt = 0; nt < 8; nt++)
                    mma_hf(acc[mt][nt], af[mt], bf[nt]);
        }
        __syncthreads();
        if (c + 2 < nch) load_stage(c + 2, c & 1);
    }

    const int erow = m0 + warp_m + (lane >> 2);
    const int ecol = n0 + warp_n + (lane & 3) * 2;
#pragma unroll
    for (int mt = 0; mt < 2; mt++) {
#pragma unroll
        for (int nt = 0; nt < 8; nt++) {
            size_t o0 = (size_t)(erow + mt * 16) * N + ecol + nt * 8;
            size_t o1 = (size_t)(erow + mt * 16 + 8) * N + ecol + nt * 8;
            *(uint32_t*)(Ch + o0) = packh2(acc[mt][nt][0], acc[mt][nt][1]);
            *(uint32_t*)(Ch + o1) = packh2(acc[mt][nt][2], acc[mt][nt][3]);
        }
    }
}

// ---------------------------------------------------------------------------
// mma.sync split-bf16 GEMM (exact path for out-projection):
// C[M,N] = A[M,K] @ Bt[N,K]^T, fp32 out.
// CTA 128x128, BK=32, 8 warps, 2-stage cp.async (2 CTAs/SM).
// ---------------------------------------------------------------------------
#define APITCH 80
#define TILE_BYTES (128 * APITCH)                 // 10240
#define STAGE_BYTES (4 * TILE_BYTES)              // 40960
#define GEMM_SMEM (2 * STAGE_BYTES)               // 81920

__global__ void __launch_bounds__(256, 2) gemm_mma(
    const __nv_bfloat16* __restrict__ Ah, const __nv_bfloat16* __restrict__ Al,
    const __nv_bfloat16* __restrict__ Bh, const __nv_bfloat16* __restrict__ Bl,
    float* __restrict__ C, int M, int N, int K)
{
    extern __shared__ char dynsm[];
    const uint32_t sm0 = smem_u32(dynsm);

    const int tid  = threadIdx.x;
    const int wid  = tid >> 5;
    const int lane = tid & 31;
    const int m0 = blockIdx.y * 128;
    const int n0 = blockIdx.x * 128;

    const int warp_m = (wid & 3) * 32;
    const int warp_n = (wid >> 2) * 64;

    const int nch = K / 32;

    auto load_stage = [&](int kc, int stage) {
        const uint32_t sb = sm0 + stage * STAGE_BYTES;
        const int ke = kc * 32;
#pragma unroll
        for (int i = 0; i < 8; i++) {
            int t = tid + i * 256;
            int tile = t >> 9;
            int r = (t >> 2) & 127;
            int j = t & 3;
            uint32_t dst = sb + tile * TILE_BYTES + r * APITCH + j * 16;
            size_t goff;
            const __nv_bfloat16* src;
            if (tile == 0)      { src = Ah; goff = (size_t)(m0 + r) * K + ke + j * 8; }
            else if (tile == 1) { src = Al; goff = (size_t)(m0 + r) * K + ke + j * 8; }
            else if (tile == 2) { src = Bh; goff = (size_t)(n0 + r) * K + ke + j * 8; }
            else                { src = Bl; goff = (size_t)(n0 + r) * K + ke + j * 8; }
            cp_async16(dst, src + goff);
        }
        CP_COMMIT();
    };

    const uint32_t a_row = warp_m + (lane & 15);
    const uint32_t a_kof = (uint32_t)(lane >> 4) * 16;
    const uint32_t b_row = warp_n + (lane & 7) + ((lane >> 4) << 3);
    const uint32_t b_kof = (uint32_t)((lane >> 3) & 1) * 16;

    float acc[2][8][4];
#pragma unroll
    for (int mt = 0; mt < 2; mt++)
#pragma unroll
        for (int nt = 0; nt < 8; nt++)
#pragma unroll
            for (int e = 0; e < 4; e++) acc[mt][nt][e] = 0.f;

    load_stage(0, 0);
    load_stage(1, 1);

    for (int c = 0; c < nch; c++) {
        if (c + 1 < nch) { CP_WAIT(1); } else { CP_WAIT(0); }
        __syncthreads();

        const uint32_t sb = sm0 + (c & 1) * STAGE_BYTES;
        const uint32_t aH = sb;
        const uint32_t aL = sb + TILE_BYTES;
        const uint32_t bH = sb + 2 * TILE_BYTES;
        const uint32_t bL = sb + 3 * TILE_BYTES;

#pragma unroll
        for (int ks = 0; ks < 2; ks++) {
            const uint32_t ks32 = ks * 32;
            uint32_t ah[2][4], al[2][4];
#pragma unroll
            for (int mt = 0; mt < 2; mt++) {
                uint32_t off = (a_row + mt * 16) * APITCH + ks32 + a_kof;
                ldsm_x4(ah[mt], aH + off);
                ldsm_x4(al[mt], aL + off);
            }
            uint32_t bh[8][2], bl[8][2];
#pragma unroll
            for (int p = 0; p < 4; p++) {
                uint32_t off = (b_row + p * 16) * APITCH + ks32 + b_kof;
                uint32_t q[4];
                ldsm_x4(q, bH + off);
                bh[2 * p][0] = q[0]; bh[2 * p][1] = q[1];
                bh[2 * p + 1][0] = q[2]; bh[2 * p + 1][1] = q[3];
                ldsm_x4(q, bL + off);
                bl[2 * p][0] = q[0]; bl[2 * p][1] = q[1];
                bl[2 * p + 1][0] = q[2]; bl[2 * p + 1][1] = q[3];
            }
#pragma unroll
            for (int mt = 0; mt < 2; mt++)
#pragma unroll
                for (int nt = 0; nt < 8; nt++) {
                    mma_bf(acc[mt][nt], ah[mt], bh[nt]);
                    mma_bf(acc[mt][nt], ah[mt], bl[nt]);
                    mma_bf(acc[mt][nt], al[mt], bh[nt]);
                }
        }
        __syncthreads();
        if (c + 2 < nch) load_stage(c + 2, c & 1);
    }

    const int erow = m0 + warp_m + (lane >> 2);
    const int ecol = n0 + warp_n + (lane & 3) * 2;
#pragma unroll
    for (int mt = 0; mt < 2; mt++) {
#pragma unroll
        for (int nt = 0; nt < 8; nt++) {
            size_t o0 = (size_t)(erow + mt * 16) * N + ecol + nt * 8;
            size_t o1 = (size_t)(erow + mt * 16 + 8) * N + ecol + nt * 8;
            *(float2*)(C + o0) = make_float2(acc[mt][nt][0], acc[mt][nt][1]);
            *(float2*)(C + o1) = make_float2(acc[mt][nt][2], acc[mt][nt][3]);
        }
    }
}

// ---------------------------------------------------------------------------
// Tensor-core flash attention, fp16 single-pass (unchanged, passing).
// ---------------------------------------------------------------------------
#define QTILE_B (128 * 128)                       // 16384
#define KVSTAGE_B (2 * 64 * 128)                  // 16384 (K + V)
#define ATT_SMEM (QTILE_B + 2 * KVSTAGE_B)        // 49152

__global__ void __launch_bounds__(128) attn_f16(
    const __half* __restrict__ qkv,
    __nv_bfloat16* __restrict__ chp, __nv_bfloat16* __restrict__ clp)
{
    extern __shared__ char smbuf[];
    const uint32_t smQ = smem_u32(smbuf);

    const int tid  = threadIdx.x;
    const int wid  = tid >> 5;
    const int lane = tid & 31;
    const int qb = gridDim.x - 1 - blockIdx.x;   // heavy blocks first
    const int b  = blockIdx.y >> 4;
    const int h  = blockIdx.y & 15;
    const int warp_m = wid * 32;
    const int nkv = 2 * qb + 2;
    const int qrow0 = qb * 128;                  // q row base (within T)

    const __half* qbase = qkv + ((size_t)b * TT + qrow0) * QKV_N + h * HD;

    // Q tile load [128 x 64 fp16], swizzled 128B rows
#pragma unroll
    for (int i = 0; i < 8; i++) {
        int t = tid + i * 128;
        int r = t >> 3, j = t & 7;
        cp_async16(smQ + sw128(r, j * 16), qbase + (size_t)r * QKV_N + j * 8);
    }
    CP_COMMIT();

    auto load_kv = [&](int jt, int st) {
        const __half* kb = qkv + ((size_t)b * TT + jt * 64) * QKV_N + h * HD;
        const uint32_t sb = smQ + QTILE_B + st * KVSTAGE_B;
#pragma unroll
        for (int i = 0; i < 8; i++) {
            int t = tid + i * 128;
            int tile = t >> 9;                    // 0 = K, 1 = V
            int r = (t >> 3) & 63, j = t & 7;
            cp_async16(sb + tile * (64 * 128) + sw128(r, j * 16),
                       kb + (size_t)r * QKV_N + (tile ? 2048 : 1024) + j * 8);
        }
        CP_COMMIT();
    };

    load_kv(0, 0);
    load_kv(1, 1);

    CP_WAIT(2);              // Q group done
    __syncthreads();

    // preload Q fragments (invariant across kv tiles)
    uint32_t qf[2][4][4];
#pragma unroll
    for (int mt = 0; mt < 2; mt++)
#pragma unroll
        for (int ks = 0; ks < 4; ks++)
            ldsm_x4(qf[mt][ks],
                    smQ + sw128(warp_m + mt * 16 + (lane & 15),
                                ks * 32 + (lane >> 4) * 16));

    float acc[2][8][4];
    float mrow[2][2], lrow[2][2];
#pragma unroll
    for (int mt = 0; mt < 2; mt++) {
#pragma unroll
        for (int hf = 0; hf < 2; hf++) { mrow[mt][hf] = -1e30f; lrow[mt][hf] = 0.f; }
#pragma unroll
        for (int nt = 0; nt < 8; nt++)
#pragma unroll
            for (int e = 0; e < 4; e++) acc[mt][nt][e] = 0.f;
    }

    const float SC = 0.18033688f;                // 0.125 * log2(e)
    const int row_lo = lane >> 2;                // row within m16 (low half)

    for (int c = 0; c < nkv; c++) {
        if (c + 1 < nkv) { CP_WAIT(1); } else { CP_WAIT(0); }
        __syncthreads();

        const uint32_t smK = smQ + QTILE_B + (c & 1) * KVSTAGE_B;
        const uint32_t smV = smK + 64 * 128;
        const bool active = (c * 64 <= qrow0 + warp_m + 31);

        if (active) {
            // ---- S = Q K^T ----
            float S[2][8][4];
#pragma unroll
            for (int mt = 0; mt < 2; mt++)
#pragma unroll
                for (int nt = 0; nt < 8; nt++)
#pragma unroll
                    for (int e = 0; e < 4; e++) S[mt][nt][e] = 0.f;

#pragma unroll
            for (int ks = 0; ks < 4; ks++) {
                uint32_t bk[8][2];
#pragma unroll
                for (int p = 0; p < 4; p++) {
                    uint32_t q[4];
                    ldsm_x4(q, smK + sw128(p * 16 + (lane & 7) + ((lane >> 4) << 3),
                                           ks * 32 + ((lane >> 3) & 1) * 16));
                    bk[2 * p][0] = q[0]; bk[2 * p][1] = q[1];
                    bk[2 * p + 1][0] = q[2]; bk[2 * p + 1][1] = q[3];
                }
#pragma unroll
                for (int mt = 0; mt < 2; mt++)
#pragma unroll
                    for (int nt = 0; nt < 8; nt++)
                        mma_hf(S[mt][nt], qf[mt][ks], bk[nt]);
            }

            // ---- scale + causal mask ----
#pragma unroll
            for (int mt = 0; mt < 2; mt++) {
                const int rbase = qrow0 + warp_m + mt * 16 + row_lo;
                const bool nm = (c * 64 + 63 > qrow0 + warp_m + mt * 16);
#pragma unroll
                for (int nt = 0; nt < 8; nt++)
#pragma unroll
                    for (int e = 0; e < 4; e++) {
                        float t = S[mt][nt][e] * SC;
                        if (nm) {
                            int col = c * 64 + nt * 8 + (lane & 3) * 2 + (e & 1);
                            int row = rbase + (e >> 1) * 8;
                            if (col > row) t = -1e30f;
                        }
                        S[mt][nt][e] = t;
                    }
            }

            // ---- online softmax ----
#pragma unroll
            for (int mt = 0; mt < 2; mt++) {
#pragma unroll
                for (int hf = 0; hf < 2; hf++) {
                    float rm = -1e30f;
#pragma unroll
                    for (int nt = 0; nt < 8; nt++) {
                        rm = fmaxf(rm, S[mt][nt][hf * 2]);
                        rm = fmaxf(rm, S[mt][nt][hf * 2 + 1]);
                    }
                    rm = fmaxf(rm, __shfl_xor_sync(0xffffffffu, rm, 1));
                    rm = fmaxf(rm, __shfl_xor_sync(0xffffffffu, rm, 2));

                    float mn = fmaxf(mrow[mt][hf], rm);
                    float alpha = ex2f(mrow[mt][hf] - mn);
                    mrow[mt][hf] = mn;

                    float rs = 0.f;
#pragma unroll
                    for (int nt = 0; nt < 8; nt++) {
                        float p0 = ex2f(S[mt][nt][hf * 2] - mn);
                        float p1 = ex2f(S[mt][nt][hf * 2 + 1] - mn);
                        S[mt][nt][hf * 2] = p0;
                        S[mt][nt][hf * 2 + 1] = p1;
                        rs += p0 + p1;
                    }
                    rs += __shfl_xor_sync(0xffffffffu, rs, 1);
                    rs += __shfl_xor_sync(0xffffffffu, rs, 2);
                    lrow[mt][hf] = lrow[mt][hf] * alpha + rs;

#pragma unroll
                    for (int nt = 0; nt < 8; nt++) {
                        acc[mt][nt][hf * 2] *= alpha;
                        acc[mt][nt][hf * 2 + 1] *= alpha;
                    }
                }
            }

            // ---- pack P -> fp16 A-fragments ----
            uint32_t pa[2][4][4];
#pragma unroll
            for (int mt = 0; mt < 2; mt++)
#pragma unroll
                for (int kk = 0; kk < 4; kk++) {
                    pa[mt][kk][0] = packh2(S[mt][2 * kk][0], S[mt][2 * kk][1]);
                    pa[mt][kk][1] = packh2(S[mt][2 * kk][2], S[mt][2 * kk][3]);
                    pa[mt][kk][2] = packh2(S[mt][2 * kk + 1][0], S[mt][2 * kk + 1][1]);
                    pa[mt][kk][3] = packh2(S[mt][2 * kk + 1][2], S[mt][2 * kk + 1][3]);
                }

            // ---- O += P V ----
#pragma unroll
            for (int ks = 0; ks < 4; ks++) {
                uint32_t bv[8][2];
#pragma unroll
                for (int nb = 0; nb < 4; nb++) {
                    uint32_t q[4];
                    ldsm_x4_t(q, smV + sw128(ks * 16 + (lane & 15),
                                             nb * 32 + ((lane >> 4) << 4)));
                    bv[2 * nb][0] = q[0]; bv[2 * nb][1] = q[1];
                    bv[2 * nb + 1][0] = q[2]; bv[2 * nb + 1][1] = q[3];
                }
#pragma unroll
                for (int mt = 0; mt < 2; mt++)
#pragma unroll
                    for (int nt = 0; nt < 8; nt++)
                        mma_hf(acc[mt][nt], pa[mt][ks], bv[nt]);
            }
        }
        __syncthreads();
        if (c + 2 < nkv) load_kv(c + 2, c & 1);
    }

    // ---- epilogue: normalize, split to bf16 hi/lo, store ----
#pragma unroll
    for (int mt = 0; mt < 2; mt++) {
#pragma unroll
        for (int hf = 0; hf < 2; hf++) {
            float inv = 1.f / lrow[mt][hf];
            int token = qrow0 + warp_m + mt * 16 + row_lo + hf * 8;
            size_t rbase = ((size_t)b * TT + token) * DD + h * HD;
#pragma unroll
            for (int nt = 0; nt < 8; nt++) {
                int col = nt * 8 + (lane & 3) * 2;
                float o0 = acc[mt][nt][hf * 2] * inv;
                float o1 = acc[mt][nt][hf * 2 + 1] * inv;
                uint32_t hi, lo;
                split2b(o0, o1, hi, lo);
                *(uint32_t*)(chp + rbase + col) = hi;
                *(uint32_t*)(clp + rbase + col) = lo;
            }
        }
    }
}

// ---------------------------------------------------------------------------
// Launch
// ---------------------------------------------------------------------------
extern "C" void kernel_launch(void* const* d_in, const int* in_sizes, int n_in,
                              void* d_out, int out_size)
{
    const float* x     = (const float*)d_in[0];
    const float* w_qkv = (const float*)d_in[2];
    const float* w_out = (const float*)d_in[3];
    float* out = (float*)d_out;

    __half *qkvh, *xf, *wqf;
    __nv_bfloat16 *woh, *wol, *ch, *cl;
    cudaGetSymbolAddress((void**)&qkvh, g_qkvh);
    cudaGetSymbolAddress((void**)&xf, g_xf);
    cudaGetSymbolAddress((void**)&wqf, g_wqf);
    cudaGetSymbolAddress((void**)&woh, g_woh);
    cudaGetSymbolAddress((void**)&wol, g_wol);
    cudaGetSymbolAddress((void**)&ch, g_ch);
    cudaGetSymbolAddress((void**)&cl, g_cl);

    cudaFuncSetAttribute(gemm_hf, cudaFuncAttributeMaxDynamicSharedMemorySize,
                         GEMMH_SMEM);
    cudaFuncSetAttribute(gemm_mma, cudaFuncAttributeMaxDynamicSharedMemorySize,
                         GEMM_SMEM);
    cudaFuncSetAttribute(attn_f16, cudaFuncAttributeMaxDynamicSharedMemorySize,
                         ATT_SMEM);

    // converts
    conv_rm<<<(ROWS * DD / 4 + 255) / 256, 256>>>((const float4*)x, xf,
                                                  ROWS * DD / 4);
    conv_tr<<<dim3(QKV_N / 32, DD / 32), dim3(32, 8)>>>(w_qkv, wqf, DD, QKV_N);
    split_tr<<<dim3(DD / 32, DD / 32), dim3(32, 8)>>>(w_out, woh, wol, DD, DD);

    // 1) QKV projection (single fp16 MMA) -> fp16 qkv
    gemm_hf<<<dim3(QKV_N / 128, ROWS / 128), 256, GEMMH_SMEM>>>(
        xf, wqf, qkvh, ROWS, QKV_N, DD);

    // 2) fused causal attention (fp16 tensor cores) -> bf16 hi/lo ctx
    attn_f16<<<dim3(TT / 128, BB * HH), 128, ATT_SMEM>>>(qkvh, ch, cl);

    // 3) output projection (split-3 bf16, exact) -> fp32 out
    gemm_mma<<<dim3(DD / 128, ROWS / 128), 256, GEMM_SMEM>>>(
        ch, cl, woh, wol, out, ROWS, DD, DD);
}

// round 13
// speedup vs baseline: 5.8665x; 1.0148x over previous
#include <cuda_runtime.h>
#include <cuda_bf16.h>
#include <cuda_fp16.h>
#include <math.h>
#include <stdint.h>

// Problem constants
#define BB 4
#define TT 1024
#define DD 1024
#define HH 16
#define HD 64
#define ROWS (BB * TT)        // 4096
#define QKV_N (3 * DD)        // 3072

// ---------------------------------------------------------------------------
// Scratch (allocation-free: __device__ globals)
// ---------------------------------------------------------------------------
__device__ __half g_qkvh[ROWS * QKV_N];           // qkv fp16 [4096, 3072]
__device__ __half g_xf[ROWS * DD];                // x fp16 [4096,1024]
__device__ __half g_wqf[QKV_N * DD];              // w_qkv^T fp16 [3072,1024]
__device__ __nv_bfloat16 g_woh[DD * DD];          // w_out^T hi/lo [1024,1024]
__device__ __nv_bfloat16 g_wol[DD * DD];
__device__ __nv_bfloat16 g_ch[ROWS * DD];         // ctx hi/lo [4096,1024]
__device__ __nv_bfloat16 g_cl[ROWS * DD];

// ---------------------------------------------------------------------------
// Baseline-PTX helpers (cp.async, ldmatrix, HMMA)
// ---------------------------------------------------------------------------
__device__ __forceinline__ uint32_t smem_u32(const void* p) {
    uint32_t a;
    asm("{ .reg .u64 t; cvta.to.shared.u64 t, %1; cvt.u32.u64 %0, t; }"
        : "=r"(a) : "l"(p));
    return a;
}
__device__ __forceinline__ void cp_async16(uint32_t dst, const void* src) {
    asm volatile("cp.async.cg.shared.global [%0], [%1], 16;\n"
                 :: "r"(dst), "l"(src));
}
#define CP_COMMIT() asm volatile("cp.async.commit_group;" ::: "memory")
#define CP_WAIT(n)  asm volatile("cp.async.wait_group %0;" :: "n"(n) : "memory")

__device__ __forceinline__ void ldsm_x4(uint32_t* r, uint32_t addr) {
    asm volatile("ldmatrix.sync.aligned.m8n8.x4.shared.b16 {%0,%1,%2,%3}, [%4];"
                 : "=r"(r[0]), "=r"(r[1]), "=r"(r[2]), "=r"(r[3]) : "r"(addr));
}
__device__ __forceinline__ void ldsm_x4_t(uint32_t* r, uint32_t addr) {
    asm volatile("ldmatrix.sync.aligned.m8n8.x4.trans.shared.b16 {%0,%1,%2,%3}, [%4];"
                 : "=r"(r[0]), "=r"(r[1]), "=r"(r[2]), "=r"(r[3]) : "r"(addr));
}
__device__ __forceinline__ void mma_bf(float* d, const uint32_t* a,
                                       const uint32_t* b) {
    asm volatile(
        "mma.sync.aligned.m16n8k16.row.col.f32.bf16.bf16.f32 "
        "{%0,%1,%2,%3}, {%4,%5,%6,%7}, {%8,%9}, {%0,%1,%2,%3};"
        : "+f"(d[0]), "+f"(d[1]), "+f"(d[2]), "+f"(d[3])
        : "r"(a[0]), "r"(a[1]), "r"(a[2]), "r"(a[3]), "r"(b[0]), "r"(b[1]));
}
__device__ __forceinline__ void mma_hf(float* d, const uint32_t* a,
                                       const uint32_t* b) {
    asm volatile(
        "mma.sync.aligned.m16n8k16.row.col.f32.f16.f16.f32 "
        "{%0,%1,%2,%3}, {%4,%5,%6,%7}, {%8,%9}, {%0,%1,%2,%3};"
        : "+f"(d[0]), "+f"(d[1]), "+f"(d[2]), "+f"(d[3])
        : "r"(a[0]), "r"(a[1]), "r"(a[2]), "r"(a[3]), "r"(b[0]), "r"(b[1]));
}
__device__ __forceinline__ float ex2f(float x) {
    float r;
    asm("ex2.approx.f32 %0, %1;" : "=f"(r) : "f"(x));
    return r;
}
// fp32 pair -> (bf16x2 hi, bf16x2 lo)
__device__ __forceinline__ void split2b(float a, float b,
                                        uint32_t& hi, uint32_t& lo) {
    __nv_bfloat162 h2 = __floats2bfloat162_rn(a, b);
    uint32_t hu = *(uint32_t*)&h2;
    float ha = __uint_as_float(hu << 16);
    float hb = __uint_as_float(hu & 0xffff0000u);
    __nv_bfloat162 l2 = __floats2bfloat162_rn(a - ha, b - hb);
    hi = hu;
    lo = *(uint32_t*)&l2;
}
__device__ __forceinline__ uint32_t packh2(float a, float b) {
    __half2 h = __floats2half2_rn(a, b);
    return *(uint32_t*)&h;
}
// SW128 swizzle for 128-byte rows: conflict-free cp.async + ldmatrix
__device__ __forceinline__ uint32_t sw128(uint32_t r, uint32_t c) {
    return r * 128u + (c ^ ((r & 7u) * 16u));
}

// ---------------------------------------------------------------------------
// convert kernels
// ---------------------------------------------------------------------------
// fp32 row-major -> fp16 row-major
__global__ void __launch_bounds__(256) conv_rm(
    const float4* __restrict__ src, __half* __restrict__ dst, int n4)
{
    int i = blockIdx.x * blockDim.x + threadIdx.x;
    if (i >= n4) return;
    float4 v = src[i];
    uint32_t* dp = reinterpret_cast<uint32_t*>(dst) + 2 * i;
    dp[0] = packh2(v.x, v.y);
    dp[1] = packh2(v.z, v.w);
}

// transpose: src [K,N] fp32 -> dst [N,K] fp16
__global__ void __launch_bounds__(256) conv_tr(
    const float* __restrict__ src, __half* __restrict__ dst, int K, int N)
{
    __shared__ float t[32][33];
    int k0 = blockIdx.y * 32, n0 = blockIdx.x * 32;
    int tx = threadIdx.x, ty = threadIdx.y;      // (32, 8)
#pragma unroll
    for (int i = 0; i < 32; i += 8)
        t[ty + i][tx] = src[(size_t)(k0 + ty + i) * N + n0 + tx];
    __syncthreads();
#pragma unroll
    for (int i = 0; i < 32; i += 8)
        dst[(size_t)(n0 + ty + i) * K + k0 + tx] = __float2half(t[tx][ty + i]);
}

// transpose + split: src [K,N] fp32 -> dst [N,K] hi/lo bf16
__global__ void __launch_bounds__(256) split_tr(
    const float* __restrict__ src, __nv_bfloat16* __restrict__ hi,
    __nv_bfloat16* __restrict__ lo, int K, int N)
{
    __shared__ float t[32][33];
    int k0 = blockIdx.y * 32, n0 = blockIdx.x * 32;
    int tx = threadIdx.x, ty = threadIdx.y;      // (32, 8)
#pragma unroll
    for (int i = 0; i < 32; i += 8)
        t[ty + i][tx] = src[(size_t)(k0 + ty + i) * N + n0 + tx];
    __syncthreads();
#pragma unroll
    for (int i = 0; i < 32; i += 8) {
        float v = t[tx][ty + i];
        __nv_bfloat16 h = __float2bfloat16(v);
        __nv_bfloat16 l = __float2bfloat16(v - __bfloat162float(h));
        size_t o = (size_t)(n0 + ty + i) * K + k0 + tx;
        hi[o] = h;
        lo[o] = l;
    }
}

// ---------------------------------------------------------------------------
// Single-fp16 GEMM: Ch[M,N] = A[M,K] @ Bt[N,K]^T   (fp16 out)
// CTA 128x128, BK=64, 8 warps (warp 32x64), 3-stage cp.async, SW128 smem.
// Early prefetch: load c+2 issued right after wait(c), overlaps compute.
// ---------------------------------------------------------------------------
#define HTILE_B (128 * 128)                       // 16384 (128 rows x 128B)
#define HSTAGE_B (2 * HTILE_B)                    // 32768 (A + B)
#define GEMMH_SMEM (3 * HSTAGE_B)                 // 98304

__global__ void __launch_bounds__(256, 2) gemm_hf(
    const __half* __restrict__ A, const __half* __restrict__ Bt,
    __half* __restrict__ Ch, int M, int N, int K)
{
    extern __shared__ char dynsm[];
    const uint32_t sm0 = smem_u32(dynsm);

    const int tid  = threadIdx.x;
    const int wid  = tid >> 5;
    const int lane = tid & 31;
    const int m0 = blockIdx.y * 128;
    const int n0 = blockIdx.x * 128;

    const int warp_m = (wid & 3) * 32;
    const int warp_n = (wid >> 2) * 64;

    const int nch = K / 64;

    auto load_stage = [&](int kc, int stage) {
        const uint32_t sb = sm0 + stage * HSTAGE_B;
        const int ke = kc * 64;
#pragma unroll
        for (int i = 0; i < 8; i++) {
            int t = tid + i * 256;
            int tile = t >> 10;                   // 0 = A, 1 = B
            int r = (t >> 3) & 127;
            int j = t & 7;
            uint32_t dst = sb + tile * HTILE_B + sw128(r, j * 16);
            const __half* src = tile ? (Bt + (size_t)(n0 + r) * K + ke + j * 8)
                                     : (A  + (size_t)(m0 + r) * K + ke + j * 8);
            cp_async16(dst, src);
        }
        CP_COMMIT();
    };

    const uint32_t a_row = warp_m + (lane & 15);
    const uint32_t a_kof = (uint32_t)(lane >> 4) * 16;
    const uint32_t b_row = warp_n + (lane & 7) + ((lane >> 4) << 3);
    const uint32_t b_kof = (uint32_t)((lane >> 3) & 1) * 16;

    float acc[2][8][4];
#pragma unroll
    for (int mt = 0; mt < 2; mt++)
#pragma unroll
        for (int nt = 0; nt < 8; nt++)
#pragma unroll
            for (int e = 0; e < 4; e++) acc[mt][nt][e] = 0.f;

    load_stage(0, 0);
    load_stage(1, 1);

    int st = 0, pf = 2;                           // compute stage, prefetch stage
    for (int c = 0; c < nch; c++) {
        if (c + 1 < nch) { CP_WAIT(1); } else { CP_WAIT(0); }
        __syncthreads();
        if (c + 2 < nch) load_stage(c + 2, pf);   // overlaps compute below

        const uint32_t sA = sm0 + st * HSTAGE_B;
        const uint32_t sB = sA + HTILE_B;

#pragma unroll
        for (int ks = 0; ks < 4; ks++) {
            const uint32_t k32 = ks * 32;         // byte offset of k-step
            uint32_t af[2][4];
#pragma unroll
            for (int mt = 0; mt < 2; mt++)
                ldsm_x4(af[mt], sA + sw128(a_row + mt * 16, k32 + a_kof));
            uint32_t bf[8][2];
#pragma unroll
            for (int p = 0; p < 4; p++) {
                uint32_t q[4];
                ldsm_x4(q, sB + sw128(b_row + p * 16, k32 + b_kof));
                bf[2 * p][0] = q[0]; bf[2 * p][1] = q[1];
                bf[2 * p + 1][0] = q[2]; bf[2 * p + 1][1] = q[3];
            }
#pragma unroll
            for (int mt = 0; mt < 2; mt++)
#pragma unroll
                for (int nt = 0; nt < 8; nt++)
                    mma_hf(acc[mt][nt], af[mt], bf[nt]);
        }
        st = (st + 1 == 3) ? 0 : st + 1;
        pf = (pf + 1 == 3) ? 0 : pf + 1;
    }

    const int erow = m0 + warp_m + (lane >> 2);
    const int ecol = n0 + warp_n + (lane & 3) * 2;
#pragma unroll
    for (int mt = 0; mt < 2; mt++) {
#pragma unroll
        for (int nt = 0; nt < 8; nt++) {
            size_t o0 = (size_t)(erow + mt * 16) * N + ecol + nt * 8;
            size_t o1 = (size_t)(erow + mt * 16 + 8) * N + ecol + nt * 8;
            *(uint32_t*)(Ch + o0) = packh2(acc[mt][nt][0], acc[mt][nt][1]);
            *(uint32_t*)(Ch + o1) = packh2(acc[mt][nt][2], acc[mt][nt][3]);
        }
    }
}

// ---------------------------------------------------------------------------
// mma.sync split-bf16 GEMM (exact path for out-projection):
// C[M,N] = A[M,K] @ Bt[N,K]^T, fp32 out.
// CTA 128x128, BK=32, 8 warps, 2-stage cp.async (2 CTAs/SM).
// ---------------------------------------------------------------------------
#define APITCH 80
#define TILE_BYTES (128 * APITCH)                 // 10240
#define STAGE_BYTES (4 * TILE_BYTES)              // 40960
#define GEMM_SMEM (2 * STAGE_BYTES)               // 81920

__global__ void __launch_bounds__(256, 2) gemm_mma(
    const __nv_bfloat16* __restrict__ Ah, const __nv_bfloat16* __restrict__ Al,
    const __nv_bfloat16* __restrict__ Bh, const __nv_bfloat16* __restrict__ Bl,
    float* __restrict__ C, int M, int N, int K)
{
    extern __shared__ char dynsm[];
    const uint32_t sm0 = smem_u32(dynsm);

    const int tid  = threadIdx.x;
    const int wid  = tid >> 5;
    const int lane = tid & 31;
    const int m0 = blockIdx.y * 128;
    const int n0 = blockIdx.x * 128;

    const int warp_m = (wid & 3) * 32;
    const int warp_n = (wid >> 2) * 64;

    const int nch = K / 32;

    auto load_stage = [&](int kc, int stage) {
        const uint32_t sb = sm0 + stage * STAGE_BYTES;
        const int ke = kc * 32;
#pragma unroll
        for (int i = 0; i < 8; i++) {
            int t = tid + i * 256;
            int tile = t >> 9;
            int r = (t >> 2) & 127;
            int j = t & 3;
            uint32_t dst = sb + tile * TILE_BYTES + r * APITCH + j * 16;
            size_t goff;
            const __nv_bfloat16* src;
            if (tile == 0)      { src = Ah; goff = (size_t)(m0 + r) * K + ke + j * 8; }
            else if (tile == 1) { src = Al; goff = (size_t)(m0 + r) * K + ke + j * 8; }
            else if (tile == 2) { src = Bh; goff = (size_t)(n0 + r) * K + ke + j * 8; }
            else                { src = Bl; goff = (size_t)(n0 + r) * K + ke + j * 8; }
            cp_async16(dst, src + goff);
        }
        CP_COMMIT();
    };

    const uint32_t a_row = warp_m + (lane & 15);
    const uint32_t a_kof = (uint32_t)(lane >> 4) * 16;
    const uint32_t b_row = warp_n + (lane & 7) + ((lane >> 4) << 3);
    const uint32_t b_kof = (uint32_t)((lane >> 3) & 1) * 16;

    float acc[2][8][4];
#pragma unroll
    for (int mt = 0; mt < 2; mt++)
#pragma unroll
        for (int nt = 0; nt < 8; nt++)
#pragma unroll
            for (int e = 0; e < 4; e++) acc[mt][nt][e] = 0.f;

    load_stage(0, 0);
    load_stage(1, 1);

    for (int c = 0; c < nch; c++) {
        if (c + 1 < nch) { CP_WAIT(1); } else { CP_WAIT(0); }
        __syncthreads();

        const uint32_t sb = sm0 + (c & 1) * STAGE_BYTES;
        const uint32_t aH = sb;
        const uint32_t aL = sb + TILE_BYTES;
        const uint32_t bH = sb + 2 * TILE_BYTES;
        const uint32_t bL = sb + 3 * TILE_BYTES;

#pragma unroll
        for (int ks = 0; ks < 2; ks++) {
            const uint32_t ks32 = ks * 32;
            uint32_t ah[2][4], al[2][4];
#pragma unroll
            for (int mt = 0; mt < 2; mt++) {
                uint32_t off = (a_row + mt * 16) * APITCH + ks32 + a_kof;
                ldsm_x4(ah[mt], aH + off);
                ldsm_x4(al[mt], aL + off);
            }
            uint32_t bh[8][2], bl[8][2];
#pragma unroll
            for (int p = 0; p < 4; p++) {
                uint32_t off = (b_row + p * 16) * APITCH + ks32 + b_kof;
                uint32_t q[4];
                ldsm_x4(q, bH + off);
                bh[2 * p][0] = q[0]; bh[2 * p][1] = q[1];
                bh[2 * p + 1][0] = q[2]; bh[2 * p + 1][1] = q[3];
                ldsm_x4(q, bL + off);
                bl[2 * p][0] = q[0]; bl[2 * p][1] = q[1];
                bl[2 * p + 1][0] = q[2]; bl[2 * p + 1][1] = q[3];
            }
#pragma unroll
            for (int mt = 0; mt < 2; mt++)
#pragma unroll
                for (int nt = 0; nt < 8; nt++) {
                    mma_bf(acc[mt][nt], ah[mt], bh[nt]);
                    mma_bf(acc[mt][nt], ah[mt], bl[nt]);
                    mma_bf(acc[mt][nt], al[mt], bh[nt]);
                }
        }
        __syncthreads();
        if (c + 2 < nch) load_stage(c + 2, c & 1);
    }

    const int erow = m0 + warp_m + (lane >> 2);
    const int ecol = n0 + warp_n + (lane & 3) * 2;
#pragma unroll
    for (int mt = 0; mt < 2; mt++) {
#pragma unroll
        for (int nt = 0; nt < 8; nt++) {
            size_t o0 = (size_t)(erow + mt * 16) * N + ecol + nt * 8;
            size_t o1 = (size_t)(erow + mt * 16 + 8) * N + ecol + nt * 8;
            *(float2*)(C + o0) = make_float2(acc[mt][nt][0], acc[mt][nt][1]);
            *(float2*)(C + o1) = make_float2(acc[mt][nt][2], acc[mt][nt][3]);
        }
    }
}

// ---------------------------------------------------------------------------
// Tensor-core flash attention, fp16 single-pass, 3-stage KV ring.
// CTA = (q-block 128, one b,h); 4 warps, warp = 32 q rows; KV tile 64.
// ---------------------------------------------------------------------------
#define QTILE_B (128 * 128)                       // 16384
#define KVSTAGE_B (2 * 64 * 128)                  // 16384 (K + V)
#define ATT_SMEM (QTILE_B + 3 * KVSTAGE_B)        // 65536

__global__ void __launch_bounds__(128) attn_f16(
    const __half* __restrict__ qkv,
    __nv_bfloat16* __restrict__ chp, __nv_bfloat16* __restrict__ clp)
{
    extern __shared__ char smbuf[];
    const uint32_t smQ = smem_u32(smbuf);

    const int tid  = threadIdx.x;
    const int wid  = tid >> 5;
    const int lane = tid & 31;
    const int qb = gridDim.x - 1 - blockIdx.x;   // heavy blocks first
    const int b  = blockIdx.y >> 4;
    const int h  = blockIdx.y & 15;
    const int warp_m = wid * 32;
    const int nkv = 2 * qb + 2;
    const int qrow0 = qb * 128;                  // q row base (within T)

    const __half* qbase = qkv + ((size_t)b * TT + qrow0) * QKV_N + h * HD;

    // Q tile load [128 x 64 fp16], swizzled 128B rows
#pragma unroll
    for (int i = 0; i < 8; i++) {
        int t = tid + i * 128;
        int r = t >> 3, j = t & 7;
        cp_async16(smQ + sw128(r, j * 16), qbase + (size_t)r * QKV_N + j * 8);
    }
    CP_COMMIT();

    auto load_kv = [&](int jt, int stg) {
        const __half* kb = qkv + ((size_t)b * TT + jt * 64) * QKV_N + h * HD;
        const uint32_t sb = smQ + QTILE_B + stg * KVSTAGE_B;
#pragma unroll
        for (int i = 0; i < 8; i++) {
            int t = tid + i * 128;
            int tile = t >> 9;                    // 0 = K, 1 = V
            int r = (t >> 3) & 63, j = t & 7;
            cp_async16(sb + tile * (64 * 128) + sw128(r, j * 16),
                       kb + (size_t)r * QKV_N + (tile ? 2048 : 1024) + j * 8);
        }
        CP_COMMIT();
    };

    load_kv(0, 0);
    load_kv(1, 1);

    CP_WAIT(2);              // Q group done
    __syncthreads();

    // preload Q fragments (invariant across kv tiles)
    uint32_t qf[2][4][4];
#pragma unroll
    for (int mt = 0; mt < 2; mt++)
#pragma unroll
        for (int ks = 0; ks < 4; ks++)
            ldsm_x4(qf[mt][ks],
                    smQ + sw128(warp_m + mt * 16 + (lane & 15),
                                ks * 32 + (lane >> 4) * 16));

    float acc[2][8][4];
    float mrow[2][2], lrow[2][2];
#pragma unroll
    for (int mt = 0; mt < 2; mt++) {
#pragma unroll
        for (int hf = 0; hf < 2; hf++) { mrow[mt][hf] = -1e30f; lrow[mt][hf] = 0.f; }
#pragma unroll
        for (int nt = 0; nt < 8; nt++)
#pragma unroll
            for (int e = 0; e < 4; e++) acc[mt][nt][e] = 0.f;
    }

    const float SC = 0.18033688f;                // 0.125 * log2(e)
    const int row_lo = lane >> 2;                // row within m16 (low half)

    int st = 0, pf = 2;
    for (int c = 0; c < nkv; c++) {
        if (c + 1 < nkv) { CP_WAIT(1); } else { CP_WAIT(0); }
        __syncthreads();
        if (c + 2 < nkv) load_kv(c + 2, pf);     // overlaps compute below

        const uint32_t smK = smQ + QTILE_B + st * KVSTAGE_B;
        const uint32_t smV = smK + 64 * 128;
        const bool active = (c * 64 <= qrow0 + warp_m + 31);

        if (active) {
            // ---- S = Q K^T ----
            float S[2][8][4];
#pragma unroll
            for (int mt = 0; mt < 2; mt++)
#pragma unroll
                for (int nt = 0; nt < 8; nt++)
#pragma unroll
                    for (int e = 0; e < 4; e++) S[mt][nt][e] = 0.f;

#pragma unroll
            for (int ks = 0; ks < 4; ks++) {
                uint32_t bk[8][2];
#pragma unroll
                for (int p = 0; p < 4; p++) {
                    uint32_t q[4];
                    ldsm_x4(q, smK + sw128(p * 16 + (lane & 7) + ((lane >> 4) << 3),
                                           ks * 32 + ((lane >> 3) & 1) * 16));
                    bk[2 * p][0] = q[0]; bk[2 * p][1] = q[1];
                    bk[2 * p + 1][0] = q[2]; bk[2 * p + 1][1] = q[3];
                }
#pragma unroll
                for (int mt = 0; mt < 2; mt++)
#pragma unroll
                    for (int nt = 0; nt < 8; nt++)
                        mma_hf(S[mt][nt], qf[mt][ks], bk[nt]);
            }

            // ---- scale + causal mask ----
#pragma unroll
            for (int mt = 0; mt < 2; mt++) {
                const int rbase = qrow0 + warp_m + mt * 16 + row_lo;
                const bool nm = (c * 64 + 63 > qrow0 + warp_m + mt * 16);
#pragma unroll
                for (int nt = 0; nt < 8; nt++)
#pragma unroll
                    for (int e = 0; e < 4; e++) {
                        float t = S[mt][nt][e] * SC;
                        if (nm) {
                            int col = c * 64 + nt * 8 + (lane & 3) * 2 + (e & 1);
                            int row = rbase + (e >> 1) * 8;
                            if (col > row) t = -1e30f;
                        }
                        S[mt][nt][e] = t;
                    }
            }

            // ---- online softmax ----
#pragma unroll
            for (int mt = 0; mt < 2; mt++) {
#pragma unroll
                for (int hf = 0; hf < 2; hf++) {
                    float rm = -1e30f;
#pragma unroll
                    for (int nt = 0; nt < 8; nt++) {
                        rm = fmaxf(rm, S[mt][nt][hf * 2]);
                        rm = fmaxf(rm, S[mt][nt][hf * 2 + 1]);
                    }
                    rm = fmaxf(rm, __shfl_xor_sync(0xffffffffu, rm, 1));
                    rm = fmaxf(rm, __shfl_xor_sync(0xffffffffu, rm, 2));

                    float mn = fmaxf(mrow[mt][hf], rm);
                    float alpha = ex2f(mrow[mt][hf] - mn);
                    mrow[mt][hf] = mn;

                    float rs = 0.f;
#pragma unroll
                    for (int nt = 0; nt < 8; nt++) {
                        float p0 = ex2f(S[mt][nt][hf * 2] - mn);
                        float p1 = ex2f(S[mt][nt][hf * 2 + 1] - mn);
                        S[mt][nt][hf * 2] = p0;
                        S[mt][nt][hf * 2 + 1] = p1;
                        rs += p0 + p1;
                    }
                    rs += __shfl_xor_sync(0xffffffffu, rs, 1);
                    rs += __shfl_xor_sync(0xffffffffu, rs, 2);
                    lrow[mt][hf] = lrow[mt][hf] * alpha + rs;

#pragma unroll
                    for (int nt = 0; nt < 8; nt++) {
                        acc[mt][nt][hf * 2] *= alpha;
                        acc[mt][nt][hf * 2 + 1] *= alpha;
                    }
                }
            }

            // ---- pack P -> fp16 A-fragments ----
            uint32_t pa[2][4][4];
#pragma unroll
            for (int mt = 0; mt < 2; mt++)
#pragma unroll
                for (int kk = 0; kk < 4; kk++) {
                    pa[mt][kk][0] = packh2(S[mt][2 * kk][0], S[mt][2 * kk][1]);
                    pa[mt][kk][1] = packh2(S[mt][2 * kk][2], S[mt][2 * kk][3]);
                    pa[mt][kk][2] = packh2(S[mt][2 * kk + 1][0], S[mt][2 * kk + 1][1]);
                    pa[mt][kk][3] = packh2(S[mt][2 * kk + 1][2], S[mt][2 * kk + 1][3]);
                }

            // ---- O += P V ----
#pragma unroll
            for (int ks = 0; ks < 4; ks++) {
                uint32_t bv[8][2];
#pragma unroll
                for (int nb = 0; nb < 4; nb++) {
                    uint32_t q[4];
                    ldsm_x4_t(q, smV + sw128(ks * 16 + (lane & 15),
                                             nb * 32 + ((lane >> 4) << 4)));
                    bv[2 * nb][0] = q[0]; bv[2 * nb][1] = q[1];
                    bv[2 * nb + 1][0] = q[2]; bv[2 * nb + 1][1] = q[3];
                }
#pragma unroll
                for (int mt = 0; mt < 2; mt++)
#pragma unroll
                    for (int nt = 0; nt < 8; nt++)
                        mma_hf(acc[mt][nt], pa[mt][ks], bv[nt]);
            }
        }
        st = (st + 1 == 3) ? 0 : st + 1;
        pf = (pf + 1 == 3) ? 0 : pf + 1;
    }

    // ---- epilogue: normalize, split to bf16 hi/lo, store ----
#pragma unroll
    for (int mt = 0; mt < 2; mt++) {
#pragma unroll
        for (int hf = 0; hf < 2; hf++) {
            float inv = 1.f / lrow[mt][hf];
            int token = qrow0 + warp_m + mt * 16 + row_lo + hf * 8;
            size_t rbase = ((size_t)b * TT + token) * DD + h * HD;
#pragma unroll
            for (int nt = 0; nt < 8; nt++) {
                int col = nt * 8 + (lane & 3) * 2;
                float o0 = acc[mt][nt][hf * 2] * inv;
                float o1 = acc[mt][nt][hf * 2 + 1] * inv;
                uint32_t hi, lo;
                split2b(o0, o1, hi, lo);
                *(uint32_t*)(chp + rbase + col) = hi;
                *(uint32_t*)(clp + rbase + col) = lo;
            }
        }
    }
}

// ---------------------------------------------------------------------------
// Launch
// ---------------------------------------------------------------------------
extern "C" void kernel_launch(void* const* d_in, const int* in_sizes, int n_in,
                              void* d_out, int out_size)
{
    const float* x     = (const float*)d_in[0];
    const float* w_qkv = (const float*)d_in[2];
    const float* w_out = (const float*)d_in[3];
    float* out = (float*)d_out;

    __half *qkvh, *xf, *wqf;
    __nv_bfloat16 *woh, *wol, *ch, *cl;
    cudaGetSymbolAddress((void**)&qkvh, g_qkvh);
    cudaGetSymbolAddress((void**)&xf, g_xf);
    cudaGetSymbolAddress((void**)&wqf, g_wqf);
    cudaGetSymbolAddress((void**)&woh, g_woh);
    cudaGetSymbolAddress((void**)&wol, g_wol);
    cudaGetSymbolAddress((void**)&ch, g_ch);
    cudaGetSymbolAddress((void**)&cl, g_cl);

    cudaFuncSetAttribute(gemm_hf, cudaFuncAttributeMaxDynamicSharedMemorySize,
                         GEMMH_SMEM);
    cudaFuncSetAttribute(gemm_mma, cudaFuncAttributeMaxDynamicSharedMemorySize,
                         GEMM_SMEM);
    cudaFuncSetAttribute(attn_f16, cudaFuncAttributeMaxDynamicSharedMemorySize,
                         ATT_SMEM);

    // converts
    conv_rm<<<(ROWS * DD / 4 + 255) / 256, 256>>>((const float4*)x, xf,
                                                  ROWS * DD / 4);
    conv_tr<<<dim3(QKV_N / 32, DD / 32), dim3(32, 8)>>>(w_qkv, wqf, DD, QKV_N);
    split_tr<<<dim3(DD / 32, DD / 32), dim3(32, 8)>>>(w_out, woh, wol, DD, DD);

    // 1) QKV projection (single fp16 MMA, 3-stage) -> fp16 qkv
    gemm_hf<<<dim3(QKV_N / 128, ROWS / 128), 256, GEMMH_SMEM>>>(
        xf, wqf, qkvh, ROWS, QKV_N, DD);

    // 2) fused causal attention (fp16 tensor cores, 3-stage KV) -> bf16 hi/lo ctx
    attn_f16<<<dim3(TT / 128, BB * HH), 128, ATT_SMEM>>>(qkvh, ch, cl);

    // 3) output projection (split-3 bf16, exact) -> fp32 out
    gemm_mma<<<dim3(DD / 128, ROWS / 128), 256, GEMM_SMEM>>>(
        ch, cl, woh, wol, out, ROWS, DD, DD);
}

// round 15
// speedup vs baseline: 8.1390x; 1.3874x over previous
#include <cuda_runtime.h>
#include <cuda_bf16.h>
#include <cuda_fp16.h>
#include <math.h>
#include <stdint.h>

// Problem constants
#define BB 4
#define TT 1024
#define DD 1024
#define HH 16
#define HD 64
#define ROWS (BB * TT)        // 4096
#define QKV_N (3 * DD)        // 3072

// ---------------------------------------------------------------------------
// Scratch (allocation-free: __device__ globals)
// ---------------------------------------------------------------------------
__device__ __half g_qkvh[ROWS * QKV_N];           // qkv fp16 [4096, 3072] (q pre-scaled)
__device__ __half g_xf[ROWS * DD];                // x fp16 [4096,1024]
__device__ __half g_wqf[QKV_N * DD];              // w_qkv^T fp16 [3072,1024]
__device__ __half g_wof[DD * DD];                 // w_out^T fp16 [1024,1024]
__device__ __half g_cf[ROWS * DD];                // ctx fp16 [4096,1024]

// ---------------------------------------------------------------------------
// Baseline-PTX helpers (cp.async, ldmatrix, HMMA)
// ---------------------------------------------------------------------------
__device__ __forceinline__ uint32_t smem_u32(const void* p) {
    uint32_t a;
    asm("{ .reg .u64 t; cvta.to.shared.u64 t, %1; cvt.u32.u64 %0, t; }"
        : "=r"(a) : "l"(p));
    return a;
}
__device__ __forceinline__ void cp_async16(uint32_t dst, const void* src) {
    asm volatile("cp.async.cg.shared.global [%0], [%1], 16;\n"
                 :: "r"(dst), "l"(src));
}
#define CP_COMMIT() asm volatile("cp.async.commit_group;" ::: "memory")
#define CP_WAIT(n)  asm volatile("cp.async.wait_group %0;" :: "n"(n) : "memory")

__device__ __forceinline__ void ldsm_x4(uint32_t* r, uint32_t addr) {
    asm volatile("ldmatrix.sync.aligned.m8n8.x4.shared.b16 {%0,%1,%2,%3}, [%4];"
                 : "=r"(r[0]), "=r"(r[1]), "=r"(r[2]), "=r"(r[3]) : "r"(addr));
}
__device__ __forceinline__ void ldsm_x4_t(uint32_t* r, uint32_t addr) {
    asm volatile("ldmatrix.sync.aligned.m8n8.x4.trans.shared.b16 {%0,%1,%2,%3}, [%4];"
                 : "=r"(r[0]), "=r"(r[1]), "=r"(r[2]), "=r"(r[3]) : "r"(addr));
}
__device__ __forceinline__ void mma_hf(float* d, const uint32_t* a,
                                       const uint32_t* b) {
    asm volatile(
        "mma.sync.aligned.m16n8k16.row.col.f32.f16.f16.f32 "
        "{%0,%1,%2,%3}, {%4,%5,%6,%7}, {%8,%9}, {%0,%1,%2,%3};"
        : "+f"(d[0]), "+f"(d[1]), "+f"(d[2]), "+f"(d[3])
        : "r"(a[0]), "r"(a[1]), "r"(a[2]), "r"(a[3]), "r"(b[0]), "r"(b[1]));
}
__device__ __forceinline__ float ex2f(float x) {
    float r;
    asm("ex2.approx.f32 %0, %1;" : "=f"(r) : "f"(x));
    return r;
}
__device__ __forceinline__ uint32_t packh2(float a, float b) {
    __half2 h = __floats2half2_rn(a, b);
    return *(uint32_t*)&h;
}
// SW128 swizzle for 128-byte rows: conflict-free cp.async + ldmatrix
__device__ __forceinline__ uint32_t sw128(uint32_t r, uint32_t c) {
    return r * 128u + (c ^ ((r & 7u) * 16u));
}

#define SCQ 0.18033688f       // 0.125 * log2(e), folded into q

// ---------------------------------------------------------------------------
// convert kernels
// ---------------------------------------------------------------------------
// fp32 row-major -> fp16 row-major
__global__ void __launch_bounds__(256) conv_rm(
    const float4* __restrict__ src, __half* __restrict__ dst, int n4)
{
    int i = blockIdx.x * blockDim.x + threadIdx.x;
    if (i >= n4) return;
    float4 v = src[i];
    uint32_t* dp = reinterpret_cast<uint32_t*>(dst) + 2 * i;
    dp[0] = packh2(v.x, v.y);
    dp[1] = packh2(v.z, v.w);
}

// transpose: src [K,N] fp32 -> dst [N,K] fp16
__global__ void __launch_bounds__(256) conv_tr(
    const float* __restrict__ src, __half* __restrict__ dst, int K, int N)
{
    __shared__ float t[32][33];
    int k0 = blockIdx.y * 32, n0 = blockIdx.x * 32;
    int tx = threadIdx.x, ty = threadIdx.y;      // (32, 8)
#pragma unroll
    for (int i = 0; i < 32; i += 8)
        t[ty + i][tx] = src[(size_t)(k0 + ty + i) * N + n0 + tx];
    __syncthreads();
#pragma unroll
    for (int i = 0; i < 32; i += 8)
        dst[(size_t)(n0 + ty + i) * K + k0 + tx] = __float2half(t[tx][ty + i]);
}

// ---------------------------------------------------------------------------
// fp16 GEMM: C/Ch[M,N] = A[M,K] @ Bt[N,K]^T
// OUT=1: fp16 out, q-region (n0<1024) scaled by SCQ.   OUT=0: fp32 out.
// CTA 128x128, BK=64, 8 warps (warp 32x64), 3-stage cp.async, SW128 smem.
// ---------------------------------------------------------------------------
#define HTILE_B (128 * 128)                       // 16384 (128 rows x 128B)
#define HSTAGE_B (2 * HTILE_B)                    // 32768 (A + B)
#define GEMMH_SMEM (3 * HSTAGE_B)                 // 98304

template <int OUT>
__global__ void __launch_bounds__(256, 2) gemm_hf(
    const __half* __restrict__ A, const __half* __restrict__ Bt,
    float* __restrict__ C, __half* __restrict__ Ch, int M, int N, int K)
{
    extern __shared__ char dynsm[];
    const uint32_t sm0 = smem_u32(dynsm);

    const int tid  = threadIdx.x;
    const int wid  = tid >> 5;
    const int lane = tid & 31;
    const int m0 = blockIdx.y * 128;
    const int n0 = blockIdx.x * 128;

    const int warp_m = (wid & 3) * 32;
    const int warp_n = (wid >> 2) * 64;

    const int nch = K / 64;
    const float osc = (OUT == 1 && n0 < 1024) ? SCQ : 1.0f;

    auto load_stage = [&](int kc, int stage) {
        const uint32_t sb = sm0 + stage * HSTAGE_B;
        const int ke = kc * 64;
#pragma unroll
        for (int i = 0; i < 8; i++) {
            int t = tid + i * 256;
            int tile = t >> 10;                   // 0 = A, 1 = B
            int r = (t >> 3) & 127;
            int j = t & 7;
            uint32_t dst = sb + tile * HTILE_B + sw128(r, j * 16);
            const __half* src = tile ? (Bt + (size_t)(n0 + r) * K + ke + j * 8)
                                     : (A  + (size_t)(m0 + r) * K + ke + j * 8);
            cp_async16(dst, src);
        }
        CP_COMMIT();
    };

    const uint32_t a_row = warp_m + (lane & 15);
    const uint32_t a_kof = (uint32_t)(lane >> 4) * 16;
    const uint32_t b_row = warp_n + (lane & 7) + ((lane >> 4) << 3);
    const uint32_t b_kof = (uint32_t)((lane >> 3) & 1) * 16;

    float acc[2][8][4];
#pragma unroll
    for (int mt = 0; mt < 2; mt++)
#pragma unroll
        for (int nt = 0; nt < 8; nt++)
#pragma unroll
            for (int e = 0; e < 4; e++) acc[mt][nt][e] = 0.f;

    load_stage(0, 0);
    load_stage(1, 1);

    int st = 0, pf = 2;                           // compute stage, prefetch stage
    for (int c = 0; c < nch; c++) {
        if (c + 1 < nch) { CP_WAIT(1); } else { CP_WAIT(0); }
        __syncthreads();
        if (c + 2 < nch) load_stage(c + 2, pf);   // overlaps compute below

        const uint32_t sA = sm0 + st * HSTAGE_B;
        const uint32_t sB = sA + HTILE_B;

#pragma unroll
        for (int ks = 0; ks < 4; ks++) {
            const uint32_t k32 = ks * 32;         // byte offset of k-step
            uint32_t af[2][4];
#pragma unroll
            for (int mt = 0; mt < 2; mt++)
                ldsm_x4(af[mt], sA + sw128(a_row + mt * 16, k32 + a_kof));
            uint32_t bf[8][2];
#pragma unroll
            for (int p = 0; p < 4; p++) {
                uint32_t q[4];
                ldsm_x4(q, sB + sw128(b_row + p * 16, k32 + b_kof));
                bf[2 * p][0] = q[0]; bf[2 * p][1] = q[1];
                bf[2 * p + 1][0] = q[2]; bf[2 * p + 1][1] = q[3];
            }
#pragma unroll
            for (int mt = 0; mt < 2; mt++)
#pragma unroll
                for (int nt = 0; nt < 8; nt++)
                    mma_hf(acc[mt][nt], af[mt], bf[nt]);
        }
        st = (st + 1 == 3) ? 0 : st + 1;
        pf = (pf + 1 == 3) ? 0 : pf + 1;
    }

    const int erow = m0 + warp_m + (lane >> 2);
    const int ecol = n0 + warp_n + (lane & 3) * 2;
#pragma unroll
    for (int mt = 0; mt < 2; mt++) {
#pragma unroll
        for (int nt = 0; nt < 8; nt++) {
            size_t o0 = (size_t)(erow + mt * 16) * N + ecol + nt * 8;
            size_t o1 = (size_t)(erow + mt * 16 + 8) * N + ecol + nt * 8;
            if (OUT == 0) {
                *(float2*)(C + o0) = make_float2(acc[mt][nt][0], acc[mt][nt][1]);
                *(float2*)(C + o1) = make_float2(acc[mt][nt][2], acc[mt][nt][3]);
            } else {
                *(uint32_t*)(Ch + o0) = packh2(acc[mt][nt][0] * osc,
                                               acc[mt][nt][1] * osc);
                *(uint32_t*)(Ch + o1) = packh2(acc[mt][nt][2] * osc,
                                               acc[mt][nt][3] * osc);
            }
        }
    }
}

// ---------------------------------------------------------------------------
// Tensor-core flash attention, fp16 single-pass, 3-stage KV ring.
// CTA = (q-block 128, one b,h); 8 warps, warp = 16 q rows; KV tile 64.
// q arrives pre-scaled by 0.125*log2(e); softmax in ex2 domain.
// Output: ctx fp16 [4096,1024].
// ---------------------------------------------------------------------------
#define QTILE_B (128 * 128)                       // 16384
#define KVSTAGE_B (2 * 64 * 128)                  // 16384 (K + V)
#define ATT_SMEM (QTILE_B + 3 * KVSTAGE_B)        // 65536

__global__ void __launch_bounds__(256, 2) attn_f16(
    const __half* __restrict__ qkv, __half* __restrict__ cf)
{
    extern __shared__ char smbuf[];
    const uint32_t smQ = smem_u32(smbuf);

    const int tid  = threadIdx.x;
    const int wid  = tid >> 5;
    const int lane = tid & 31;
    const int qb = gridDim.x - 1 - blockIdx.x;   // heavy blocks first
    const int b  = blockIdx.y >> 4;
    const int h  = blockIdx.y & 15;
    const int warp_m = wid * 16;                 // 8 warps x 16 rows
    const int nkv = 2 * qb + 2;
    const int qrow0 = qb * 128;                  // q row base (within T)

    const __half* qbase = qkv + ((size_t)b * TT + qrow0) * QKV_N + h * HD;

    // Q tile load [128 x 64 fp16], swizzled 128B rows (1024 chunks, 256 thr)
#pragma unroll
    for (int i = 0; i < 4; i++) {
        int t = tid + i * 256;
        int r = t >> 3, j = t & 7;
        cp_async16(smQ + sw128(r, j * 16), qbase + (size_t)r * QKV_N + j * 8);
    }
    CP_COMMIT();

    auto load_kv = [&](int jt, int stg) {
        const __half* kb = qkv + ((size_t)b * TT + jt * 64) * QKV_N + h * HD;
        const uint32_t sb = smQ + QTILE_B + stg * KVSTAGE_B;
#pragma unroll
        for (int i = 0; i < 4; i++) {
            int t = tid + i * 256;
            int tile = t >> 9;                    // 0 = K, 1 = V
            int r = (t >> 3) & 63, j = t & 7;
            cp_async16(sb + tile * (64 * 128) + sw128(r, j * 16),
                       kb + (size_t)r * QKV_N + (tile ? 2048 : 1024) + j * 8);
        }
        CP_COMMIT();
    };

    load_kv(0, 0);
    load_kv(1, 1);

    CP_WAIT(2);              // Q group done
    __syncthreads();

    // preload Q fragments (invariant across kv tiles)
    uint32_t qf[4][4];
#pragma unroll
    for (int ks = 0; ks < 4; ks++)
        ldsm_x4(qf[ks], smQ + sw128(warp_m + (lane & 15),
                                    ks * 32 + (lane >> 4) * 16));

    float acc[8][4];
    float mrow[2], lrow[2];
#pragma unroll
    for (int hf = 0; hf < 2; hf++) { mrow[hf] = -1e30f; lrow[hf] = 0.f; }
#pragma unroll
    for (int nt = 0; nt < 8; nt++)
#pragma unroll
        for (int e = 0; e < 4; e++) acc[nt][e] = 0.f;

    const int row_lo = lane >> 2;                // row within m16 (low half)

    int st = 0, pf = 2;
    for (int c = 0; c < nkv; c++) {
        if (c + 1 < nkv) { CP_WAIT(1); } else { CP_WAIT(0); }
        __syncthreads();
        if (c + 2 < nkv) load_kv(c + 2, pf);     // overlaps compute below

        const uint32_t smK = smQ + QTILE_B + st * KVSTAGE_B;
        const uint32_t smV = smK + 64 * 128;
        const bool active = (c * 64 <= qrow0 + warp_m + 15);

        if (active) {
            // ---- S = Q K^T (q pre-scaled, t-domain) ----
            float S[8][4];
#pragma unroll
            for (int nt = 0; nt < 8; nt++)
#pragma unroll
                for (int e = 0; e < 4; e++) S[nt][e] = 0.f;

#pragma unroll
            for (int ks = 0; ks < 4; ks++) {
                uint32_t bk[8][2];
#pragma unroll
                for (int p = 0; p < 4; p++) {
                    uint32_t q[4];
                    ldsm_x4(q, smK + sw128(p * 16 + (lane & 7) + ((lane >> 4) << 3),
                                           ks * 32 + ((lane >> 3) & 1) * 16));
                    bk[2 * p][0] = q[0]; bk[2 * p][1] = q[1];
                    bk[2 * p + 1][0] = q[2]; bk[2 * p + 1][1] = q[3];
                }
#pragma unroll
                for (int nt = 0; nt < 8; nt++)
                    mma_hf(S[nt], qf[ks], bk[nt]);
            }

            // ---- causal mask (diagonal tiles only) ----
            const bool nm = (c * 64 + 63 > qrow0 + warp_m);
            if (nm) {
                const int rbase = qrow0 + warp_m + row_lo;
#pragma unroll
                for (int nt = 0; nt < 8; nt++)
#pragma unroll
                    for (int e = 0; e < 4; e++) {
                        int col = c * 64 + nt * 8 + (lane & 3) * 2 + (e & 1);
                        int row = rbase + (e >> 1) * 8;
                        if (col > row) S[nt][e] = -1e30f;
                    }
            }

            // ---- online softmax ----
#pragma unroll
            for (int hf = 0; hf < 2; hf++) {
                float rm = -1e30f;
#pragma unroll
                for (int nt = 0; nt < 8; nt++) {
                    rm = fmaxf(rm, S[nt][hf * 2]);
                    rm = fmaxf(rm, S[nt][hf * 2 + 1]);
                }
                rm = fmaxf(rm, __shfl_xor_sync(0xffffffffu, rm, 1));
                rm = fmaxf(rm, __shfl_xor_sync(0xffffffffu, rm, 2));

                float mn = fmaxf(mrow[hf], rm);
                float alpha = ex2f(mrow[hf] - mn);
                mrow[hf] = mn;

                float rs = 0.f;
#pragma unroll
                for (int nt = 0; nt < 8; nt++) {
                    float p0 = ex2f(S[nt][hf * 2] - mn);
                    float p1 = ex2f(S[nt][hf * 2 + 1] - mn);
                    S[nt][hf * 2] = p0;
                    S[nt][hf * 2 + 1] = p1;
                    rs += p0 + p1;
                }
                rs += __shfl_xor_sync(0xffffffffu, rs, 1);
                rs += __shfl_xor_sync(0xffffffffu, rs, 2);
                lrow[hf] = lrow[hf] * alpha + rs;

#pragma unroll
                for (int nt = 0; nt < 8; nt++) {
                    acc[nt][hf * 2] *= alpha;
                    acc[nt][hf * 2 + 1] *= alpha;
                }
            }

            // ---- pack P -> fp16 A-fragments ----
            uint32_t pa[4][4];
#pragma unroll
            for (int kk = 0; kk < 4; kk++) {
                pa[kk][0] = packh2(S[2 * kk][0], S[2 * kk][1]);
                pa[kk][1] = packh2(S[2 * kk][2], S[2 * kk][3]);
                pa[kk][2] = packh2(S[2 * kk + 1][0], S[2 * kk + 1][1]);
                pa[kk][3] = packh2(S[2 * kk + 1][2], S[2 * kk + 1][3]);
            }

            // ---- O += P V ----
#pragma unroll
            for (int ks = 0; ks < 4; ks++) {
                uint32_t bv[8][2];
#pragma unroll
                for (int nb = 0; nb < 4; nb++) {
                    uint32_t q[4];
                    ldsm_x4_t(q, smV + sw128(ks * 16 + (lane & 15),
                                             nb * 32 + ((lane >> 4) << 4)));
                    bv[2 * nb][0] = q[0]; bv[2 * nb][1] = q[1];
                    bv[2 * nb + 1][0] = q[2]; bv[2 * nb + 1][1] = q[3];
                }
#pragma unroll
                for (int nt = 0; nt < 8; nt++)
                    mma_hf(acc[nt], pa[ks], bv[nt]);
            }
        }
        st = (st + 1 == 3) ? 0 : st + 1;
        pf = (pf + 1 == 3) ? 0 : pf + 1;
    }

    // ---- epilogue: normalize, store fp16 ctx ----
#pragma unroll
    for (int hf = 0; hf < 2; hf++) {
        float inv = 1.f / lrow[hf];
        int token = qrow0 + warp_m + row_lo + hf * 8;
        size_t rbase = ((size_t)b * TT + token) * DD + h * HD;
#pragma unroll
        for (int nt = 0; nt < 8; nt++) {
            int col = nt * 8 + (lane & 3) * 2;
            *(uint32_t*)(cf + rbase + col) =
                packh2(acc[nt][hf * 2] * inv, acc[nt][hf * 2 + 1] * inv);
        }
    }
}

// ---------------------------------------------------------------------------
// Launch
// ---------------------------------------------------------------------------
extern "C" void kernel_launch(void* const* d_in, const int* in_sizes, int n_in,
                              void* d_out, int out_size)
{
    const float* x     = (const float*)d_in[0];
    const float* w_qkv = (const float*)d_in[2];
    const float* w_out = (const float*)d_in[3];
    float* out = (float*)d_out;

    __half *qkvh, *xf, *wqf, *wof, *cf;
    cudaGetSymbolAddress((void**)&qkvh, g_qkvh);
    cudaGetSymbolAddress((void**)&xf, g_xf);
    cudaGetSymbolAddress((void**)&wqf, g_wqf);
    cudaGetSymbolAddress((void**)&wof, g_wof);
    cudaGetSymbolAddress((void**)&cf, g_cf);

    cudaFuncSetAttribute(gemm_hf<0>, cudaFuncAttributeMaxDynamicSharedMemorySize,
                         GEMMH_SMEM);
    cudaFuncSetAttribute(gemm_hf<1>, cudaFuncAttributeMaxDynamicSharedMemorySize,
                         GEMMH_SMEM);
    cudaFuncSetAttribute(attn_f16, cudaFuncAttributeMaxDynamicSharedMemorySize,
                         ATT_SMEM);

    // converts
    conv_rm<<<(ROWS * DD / 4 + 255) / 256, 256>>>((const float4*)x, xf,
                                                  ROWS * DD / 4);
    conv_tr<<<dim3(QKV_N / 32, DD / 32), dim3(32, 8)>>>(w_qkv, wqf, DD, QKV_N);
    conv_tr<<<dim3(DD / 32, DD / 32), dim3(32, 8)>>>(w_out, wof, DD, DD);

    // 1) QKV projection (fp16 MMA, q pre-scaled) -> fp16 qkv
    gemm_hf<1><<<dim3(QKV_N / 128, ROWS / 128), 256, GEMMH_SMEM>>>(
        xf, wqf, nullptr, qkvh, ROWS, QKV_N, DD);

    // 2) fused causal attention (fp16 tensor cores, 8 warps) -> fp16 ctx
    attn_f16<<<dim3(TT / 128, BB * HH), 256, ATT_SMEM>>>(qkvh, cf);

    // 3) output projection (fp16 MMA) -> fp32 out
    gemm_hf<0><<<dim3(DD / 128, ROWS / 128), 256, GEMMH_SMEM>>>(
        cf, wof, out, nullptr, ROWS, DD, DD);
}

// round 16
// speedup vs baseline: 8.1887x; 1.0061x over previous
#include <cuda_runtime.h>
#include <cuda_bf16.h>
#include <cuda_fp16.h>
#include <math.h>
#include <stdint.h>

// Problem constants
#define BB 4
#define TT 1024
#define DD 1024
#define HH 16
#define HD 64
#define ROWS (BB * TT)        // 4096
#define QKV_N (3 * DD)        // 3072

// ---------------------------------------------------------------------------
// Scratch (allocation-free: __device__ globals)
// ---------------------------------------------------------------------------
__device__ __half g_qkvh[ROWS * QKV_N];           // qkv fp16 [4096, 3072] (q pre-scaled)
__device__ __half g_xf[ROWS * DD];                // x fp16 [4096,1024]
__device__ __half g_wqf[QKV_N * DD];              // w_qkv^T fp16 [3072,1024]
__device__ __half g_wof[DD * DD];                 // w_out^T fp16 [1024,1024]
__device__ __half g_cf[ROWS * DD];                // ctx fp16 [4096,1024]

// ---------------------------------------------------------------------------
// Baseline-PTX helpers (cp.async, ldmatrix, HMMA)
// ---------------------------------------------------------------------------
__device__ __forceinline__ uint32_t smem_u32(const void* p) {
    uint32_t a;
    asm("{ .reg .u64 t; cvta.to.shared.u64 t, %1; cvt.u32.u64 %0, t; }"
        : "=r"(a) : "l"(p));
    return a;
}
__device__ __forceinline__ void cp_async16(uint32_t dst, const void* src) {
    asm volatile("cp.async.cg.shared.global [%0], [%1], 16;\n"
                 :: "r"(dst), "l"(src));
}
#define CP_COMMIT() asm volatile("cp.async.commit_group;" ::: "memory")
#define CP_WAIT(n)  asm volatile("cp.async.wait_group %0;" :: "n"(n) : "memory")

__device__ __forceinline__ void ldsm_x4(uint32_t* r, uint32_t addr) {
    asm volatile("ldmatrix.sync.aligned.m8n8.x4.shared.b16 {%0,%1,%2,%3}, [%4];"
                 : "=r"(r[0]), "=r"(r[1]), "=r"(r[2]), "=r"(r[3]) : "r"(addr));
}
__device__ __forceinline__ void ldsm_x4_t(uint32_t* r, uint32_t addr) {
    asm volatile("ldmatrix.sync.aligned.m8n8.x4.trans.shared.b16 {%0,%1,%2,%3}, [%4];"
                 : "=r"(r[0]), "=r"(r[1]), "=r"(r[2]), "=r"(r[3]) : "r"(addr));
}
__device__ __forceinline__ void mma_hf(float* d, const uint32_t* a,
                                       const uint32_t* b) {
    asm volatile(
        "mma.sync.aligned.m16n8k16.row.col.f32.f16.f16.f32 "
        "{%0,%1,%2,%3}, {%4,%5,%6,%7}, {%8,%9}, {%0,%1,%2,%3};"
        : "+f"(d[0]), "+f"(d[1]), "+f"(d[2]), "+f"(d[3])
        : "r"(a[0]), "r"(a[1]), "r"(a[2]), "r"(a[3]), "r"(b[0]), "r"(b[1]));
}
__device__ __forceinline__ float ex2f(float x) {
    float r;
    asm("ex2.approx.f32 %0, %1;" : "=f"(r) : "f"(x));
    return r;
}
__device__ __forceinline__ uint32_t packh2(float a, float b) {
    __half2 h = __floats2half2_rn(a, b);
    return *(uint32_t*)&h;
}
// SW128 swizzle for 128-byte rows: conflict-free cp.async + ldmatrix
__device__ __forceinline__ uint32_t sw128(uint32_t r, uint32_t c) {
    return r * 128u + (c ^ ((r & 7u) * 16u));
}

#define SCQ 0.18033688f       // 0.125 * log2(e), folded into q

// ---------------------------------------------------------------------------
// convert kernels
// ---------------------------------------------------------------------------
// fp32 row-major -> fp16 row-major
__global__ void __launch_bounds__(256) conv_rm(
    const float4* __restrict__ src, __half* __restrict__ dst, int n4)
{
    int i = blockIdx.x * blockDim.x + threadIdx.x;
    if (i >= n4) return;
    float4 v = src[i];
    uint32_t* dp = reinterpret_cast<uint32_t*>(dst) + 2 * i;
    dp[0] = packh2(v.x, v.y);
    dp[1] = packh2(v.z, v.w);
}

// transpose: src [K,N] fp32 -> dst [N,K] fp16
__global__ void __launch_bounds__(256) conv_tr(
    const float* __restrict__ src, __half* __restrict__ dst, int K, int N)
{
    __shared__ float t[32][33];
    int k0 = blockIdx.y * 32, n0 = blockIdx.x * 32;
    int tx = threadIdx.x, ty = threadIdx.y;      // (32, 8)
#pragma unroll
    for (int i = 0; i < 32; i += 8)
        t[ty + i][tx] = src[(size_t)(k0 + ty + i) * N + n0 + tx];
    __syncthreads();
#pragma unroll
    for (int i = 0; i < 32; i += 8)
        dst[(size_t)(n0 + ty + i) * K + k0 + tx] = __float2half(t[tx][ty + i]);
}

// ---------------------------------------------------------------------------
// fp16 GEMM: C/Ch[M,N] = A[M,K] @ Bt[N,K]^T
// OUT=1: fp16 out, q-region (n0<1024) scaled by SCQ.   OUT=0: fp32 out.
// CTA 128x128, BK=64, 8 warps (warp 32x64), 3-stage cp.async, SW128 smem.
// Inner loop: double-buffered fragments -- ldsm(ks+1) issued before MMA(ks)
// so LSU and tensor pipes overlap instead of oscillating.
// ---------------------------------------------------------------------------
#define HTILE_B (128 * 128)                       // 16384 (128 rows x 128B)
#define HSTAGE_B (2 * HTILE_B)                    // 32768 (A + B)
#define GEMMH_SMEM (3 * HSTAGE_B)                 // 98304

template <int OUT>
__global__ void __launch_bounds__(256, 2) gemm_hf(
    const __half* __restrict__ A, const __half* __restrict__ Bt,
    float* __restrict__ C, __half* __restrict__ Ch, int M, int N, int K)
{
    extern __shared__ char dynsm[];
    const uint32_t sm0 = smem_u32(dynsm);

    const int tid  = threadIdx.x;
    const int wid  = tid >> 5;
    const int lane = tid & 31;
    const int m0 = blockIdx.y * 128;
    const int n0 = blockIdx.x * 128;

    const int warp_m = (wid & 3) * 32;
    const int warp_n = (wid >> 2) * 64;

    const int nch = K / 64;
    const float osc = (OUT == 1 && n0 < 1024) ? SCQ : 1.0f;

    auto load_stage = [&](int kc, int stage) {
        const uint32_t sb = sm0 + stage * HSTAGE_B;
        const int ke = kc * 64;
#pragma unroll
        for (int i = 0; i < 8; i++) {
            int t = tid + i * 256;
            int tile = t >> 10;                   // 0 = A, 1 = B
            int r = (t >> 3) & 127;
            int j = t & 7;
            uint32_t dst = sb + tile * HTILE_B + sw128(r, j * 16);
            const __half* src = tile ? (Bt + (size_t)(n0 + r) * K + ke + j * 8)
                                     : (A  + (size_t)(m0 + r) * K + ke + j * 8);
            cp_async16(dst, src);
        }
        CP_COMMIT();
    };

    const uint32_t a_row = warp_m + (lane & 15);
    const uint32_t a_kof = (uint32_t)(lane >> 4) * 16;
    const uint32_t b_row = warp_n + (lane & 7) + ((lane >> 4) << 3);
    const uint32_t b_kof = (uint32_t)((lane >> 3) & 1) * 16;

    float acc[2][8][4];
#pragma unroll
    for (int mt = 0; mt < 2; mt++)
#pragma unroll
        for (int nt = 0; nt < 8; nt++)
#pragma unroll
            for (int e = 0; e < 4; e++) acc[mt][nt][e] = 0.f;

    load_stage(0, 0);
    load_stage(1, 1);

    // double-buffered fragments
    uint32_t afb[2][2][4];                        // [buf][mt][4]
    uint32_t bfb[2][8][2];                        // [buf][nt][2]

    auto load_frags = [&](uint32_t sA, uint32_t sB, int ks, int buf) {
        const uint32_t k32 = (uint32_t)ks * 32;
#pragma unroll
        for (int mt = 0; mt < 2; mt++)
            ldsm_x4(afb[buf][mt], sA + sw128(a_row + mt * 16, k32 + a_kof));
#pragma unroll
        for (int p = 0; p < 4; p++) {
            uint32_t q[4];
            ldsm_x4(q, sB + sw128(b_row + p * 16, k32 + b_kof));
            bfb[buf][2 * p][0] = q[0]; bfb[buf][2 * p][1] = q[1];
            bfb[buf][2 * p + 1][0] = q[2]; bfb[buf][2 * p + 1][1] = q[3];
        }
    };

    int st = 0, pf = 2;                           // compute stage, prefetch stage
    for (int c = 0; c < nch; c++) {
        if (c + 1 < nch) { CP_WAIT(1); } else { CP_WAIT(0); }
        __syncthreads();
        if (c + 2 < nch) load_stage(c + 2, pf);   // overlaps compute below

        const uint32_t sA = sm0 + st * HSTAGE_B;
        const uint32_t sB = sA + HTILE_B;

        load_frags(sA, sB, 0, 0);
#pragma unroll
        for (int ks = 0; ks < 4; ks++) {
            if (ks < 3) load_frags(sA, sB, ks + 1, (ks + 1) & 1);
            const int cb = ks & 1;
#pragma unroll
            for (int mt = 0; mt < 2; mt++)
#pragma unroll
                for (int nt = 0; nt < 8; nt++)
                    mma_hf(acc[mt][nt], afb[cb][mt], bfb[cb][nt]);
        }
        st = (st + 1 == 3) ? 0 : st + 1;
        pf = (pf + 1 == 3) ? 0 : pf + 1;
    }

    const int erow = m0 + warp_m + (lane >> 2);
    const int ecol = n0 + warp_n + (lane & 3) * 2;
#pragma unroll
    for (int mt = 0; mt < 2; mt++) {
#pragma unroll
        for (int nt = 0; nt < 8; nt++) {
            size_t o0 = (size_t)(erow + mt * 16) * N + ecol + nt * 8;
            size_t o1 = (size_t)(erow + mt * 16 + 8) * N + ecol + nt * 8;
            if (OUT == 0) {
                *(float2*)(C + o0) = make_float2(acc[mt][nt][0], acc[mt][nt][1]);
                *(float2*)(C + o1) = make_float2(acc[mt][nt][2], acc[mt][nt][3]);
            } else {
                *(uint32_t*)(Ch + o0) = packh2(acc[mt][nt][0] * osc,
                                               acc[mt][nt][1] * osc);
                *(uint32_t*)(Ch + o1) = packh2(acc[mt][nt][2] * osc,
                                               acc[mt][nt][3] * osc);
            }
        }
    }
}

// ---------------------------------------------------------------------------
// Tensor-core flash attention, fp16 single-pass, 3-stage KV ring.
// CTA = (q-block 128, one b,h); 8 warps, warp = 16 q rows; KV tile 64.
// q arrives pre-scaled by 0.125*log2(e); softmax in ex2 domain.
// Output: ctx fp16 [4096,1024].
// ---------------------------------------------------------------------------
#define QTILE_B (128 * 128)                       // 16384
#define KVSTAGE_B (2 * 64 * 128)                  // 16384 (K + V)
#define ATT_SMEM (QTILE_B + 3 * KVSTAGE_B)        // 65536

__global__ void __launch_bounds__(256, 2) attn_f16(
    const __half* __restrict__ qkv, __half* __restrict__ cf)
{
    extern __shared__ char smbuf[];
    const uint32_t smQ = smem_u32(smbuf);

    const int tid  = threadIdx.x;
    const int wid  = tid >> 5;
    const int lane = tid & 31;
    const int qb = gridDim.x - 1 - blockIdx.x;   // heavy blocks first
    const int b  = blockIdx.y >> 4;
    const int h  = blockIdx.y & 15;
    const int warp_m = wid * 16;                 // 8 warps x 16 rows
    const int nkv = 2 * qb + 2;
    const int qrow0 = qb * 128;                  // q row base (within T)

    const __half* qbase = qkv + ((size_t)b * TT + qrow0) * QKV_N + h * HD;

    // Q tile load [128 x 64 fp16], swizzled 128B rows (1024 chunks, 256 thr)
#pragma unroll
    for (int i = 0; i < 4; i++) {
        int t = tid + i * 256;
        int r = t >> 3, j = t & 7;
        cp_async16(smQ + sw128(r, j * 16), qbase + (size_t)r * QKV_N + j * 8);
    }
    CP_COMMIT();

    auto load_kv = [&](int jt, int stg) {
        const __half* kb = qkv + ((size_t)b * TT + jt * 64) * QKV_N + h * HD;
        const uint32_t sb = smQ + QTILE_B + stg * KVSTAGE_B;
#pragma unroll
        for (int i = 0; i < 4; i++) {
            int t = tid + i * 256;
            int tile = t >> 9;                    // 0 = K, 1 = V
            int r = (t >> 3) & 63, j = t & 7;
            cp_async16(sb + tile * (64 * 128) + sw128(r, j * 16),
                       kb + (size_t)r * QKV_N + (tile ? 2048 : 1024) + j * 8);
        }
        CP_COMMIT();
    };

    load_kv(0, 0);
    load_kv(1, 1);

    CP_WAIT(2);              // Q group done
    __syncthreads();

    // preload Q fragments (invariant across kv tiles)
    uint32_t qf[4][4];
#pragma unroll
    for (int ks = 0; ks < 4; ks++)
        ldsm_x4(qf[ks], smQ + sw128(warp_m + (lane & 15),
                                    ks * 32 + (lane >> 4) * 16));

    float acc[8][4];
    float mrow[2], lrow[2];
#pragma unroll
    for (int hf = 0; hf < 2; hf++) { mrow[hf] = -1e30f; lrow[hf] = 0.f; }
#pragma unroll
    for (int nt = 0; nt < 8; nt++)
#pragma unroll
        for (int e = 0; e < 4; e++) acc[nt][e] = 0.f;

    const int row_lo = lane >> 2;                // row within m16 (low half)

    int st = 0, pf = 2;
    for (int c = 0; c < nkv; c++) {
        if (c + 1 < nkv) { CP_WAIT(1); } else { CP_WAIT(0); }
        __syncthreads();
        if (c + 2 < nkv) load_kv(c + 2, pf);     // overlaps compute below

        const uint32_t smK = smQ + QTILE_B + st * KVSTAGE_B;
        const uint32_t smV = smK + 64 * 128;
        const bool active = (c * 64 <= qrow0 + warp_m + 15);

        if (active) {
            // ---- S = Q K^T (q pre-scaled, t-domain) ----
            float S[8][4];
#pragma unroll
            for (int nt = 0; nt < 8; nt++)
#pragma unroll
                for (int e = 0; e < 4; e++) S[nt][e] = 0.f;

#pragma unroll
            for (int ks = 0; ks < 4; ks++) {
                uint32_t bk[8][2];
#pragma unroll
                for (int p = 0; p < 4; p++) {
                    uint32_t q[4];
                    ldsm_x4(q, smK + sw128(p * 16 + (lane & 7) + ((lane >> 4) << 3),
                                           ks * 32 + ((lane >> 3) & 1) * 16));
                    bk[2 * p][0] = q[0]; bk[2 * p][1] = q[1];
                    bk[2 * p + 1][0] = q[2]; bk[2 * p + 1][1] = q[3];
                }
#pragma unroll
                for (int nt = 0; nt < 8; nt++)
                    mma_hf(S[nt], qf[ks], bk[nt]);
            }

            // ---- causal mask (diagonal tiles only) ----
            const bool nm = (c * 64 + 63 > qrow0 + warp_m);
            if (nm) {
                const int rbase = qrow0 + warp_m + row_lo;
#pragma unroll
                for (int nt = 0; nt < 8; nt++)
#pragma unroll
                    for (int e = 0; e < 4; e++) {
                        int col = c * 64 + nt * 8 + (lane & 3) * 2 + (e & 1);
                        int row = rbase + (e >> 1) * 8;
                        if (col > row) S[nt][e] = -1e30f;
                    }
            }

            // ---- online softmax ----
#pragma unroll
            for (int hf = 0; hf < 2; hf++) {
                float rm = -1e30f;
#pragma unroll
                for (int nt = 0; nt < 8; nt++) {
                    rm = fmaxf(rm, S[nt][hf * 2]);
                    rm = fmaxf(rm, S[nt][hf * 2 + 1]);
                }
                rm = fmaxf(rm, __shfl_xor_sync(0xffffffffu, rm, 1));
                rm = fmaxf(rm, __shfl_xor_sync(0xffffffffu, rm, 2));

                float mn = fmaxf(mrow[hf], rm);
                float alpha = ex2f(mrow[hf] - mn);
                mrow[hf] = mn;

                float rs = 0.f;
#pragma unroll
                for (int nt = 0; nt < 8; nt++) {
                    float p0 = ex2f(S[nt][hf * 2] - mn);
                    float p1 = ex2f(S[nt][hf * 2 + 1] - mn);
                    S[nt][hf * 2] = p0;
                    S[nt][hf * 2 + 1] = p1;
                    rs += p0 + p1;
                }
                rs += __shfl_xor_sync(0xffffffffu, rs, 1);
                rs += __shfl_xor_sync(0xffffffffu, rs, 2);
                lrow[hf] = lrow[hf] * alpha + rs;

#pragma unroll
                for (int nt = 0; nt < 8; nt++) {
                    acc[nt][hf * 2] *= alpha;
                    acc[nt][hf * 2 + 1] *= alpha;
                }
            }

            // ---- pack P -> fp16 A-fragments ----
            uint32_t pa[4][4];
#pragma unroll
            for (int kk = 0; kk < 4; kk++) {
                pa[kk][0] = packh2(S[2 * kk][0], S[2 * kk][1]);
                pa[kk][1] = packh2(S[2 * kk][2], S[2 * kk][3]);
                pa[kk][2] = packh2(S[2 * kk + 1][0], S[2 * kk + 1][1]);
                pa[kk][3] = packh2(S[2 * kk + 1][2], S[2 * kk + 1][3]);
            }

            // ---- O += P V ----
#pragma unroll
            for (int ks = 0; ks < 4; ks++) {
                uint32_t bv[8][2];
#pragma unroll
                for (int nb = 0; nb < 4; nb++) {
                    uint32_t q[4];
                    ldsm_x4_t(q, smV + sw128(ks * 16 + (lane & 15),
                                             nb * 32 + ((lane >> 4) << 4)));
                    bv[2 * nb][0] = q[0]; bv[2 * nb][1] = q[1];
                    bv[2 * nb + 1][0] = q[2]; bv[2 * nb + 1][1] = q[3];
                }
#pragma unroll
                for (int nt = 0; nt < 8; nt++)
                    mma_hf(acc[nt], pa[ks], bv[nt]);
            }
        }
        st = (st + 1 == 3) ? 0 : st + 1;
        pf = (pf + 1 == 3) ? 0 : pf + 1;
    }

    // ---- epilogue: normalize, store fp16 ctx ----
#pragma unroll
    for (int hf = 0; hf < 2; hf++) {
        float inv = 1.f / lrow[hf];
        int token = qrow0 + warp_m + row_lo + hf * 8;
        size_t rbase = ((size_t)b * TT + token) * DD + h * HD;
#pragma unroll
        for (int nt = 0; nt < 8; nt++) {
            int col = nt * 8 + (lane & 3) * 2;
            *(uint32_t*)(cf + rbase + col) =
                packh2(acc[nt][hf * 2] * inv, acc[nt][hf * 2 + 1] * inv);
        }
    }
}

// ---------------------------------------------------------------------------
// Launch
// ---------------------------------------------------------------------------
extern "C" void kernel_launch(void* const* d_in, const int* in_sizes, int n_in,
                              void* d_out, int out_size)
{
    const float* x     = (const float*)d_in[0];
    const float* w_qkv = (const float*)d_in[2];
    const float* w_out = (const float*)d_in[3];
    float* out = (float*)d_out;

    __half *qkvh, *xf, *wqf, *wof, *cf;
    cudaGetSymbolAddress((void**)&qkvh, g_qkvh);
    cudaGetSymbolAddress((void**)&xf, g_xf);
    cudaGetSymbolAddress((void**)&wqf, g_wqf);
    cudaGetSymbolAddress((void**)&wof, g_wof);
    cudaGetSymbolAddress((void**)&cf, g_cf);

    cudaFuncSetAttribute(gemm_hf<0>, cudaFuncAttributeMaxDynamicSharedMemorySize,
                         GEMMH_SMEM);
    cudaFuncSetAttribute(gemm_hf<1>, cudaFuncAttributeMaxDynamicSharedMemorySize,
                         GEMMH_SMEM);
    cudaFuncSetAttribute(attn_f16, cudaFuncAttributeMaxDynamicSharedMemorySize,
                         ATT_SMEM);

    // converts
    conv_rm<<<(ROWS * DD / 4 + 255) / 256, 256>>>((const float4*)x, xf,
                                                  ROWS * DD / 4);
    conv_tr<<<dim3(QKV_N / 32, DD / 32), dim3(32, 8)>>>(w_qkv, wqf, DD, QKV_N);
    conv_tr<<<dim3(DD / 32, DD / 32), dim3(32, 8)>>>(w_out, wof, DD, DD);

    // 1) QKV projection (fp16 MMA, q pre-scaled) -> fp16 qkv
    gemm_hf<1><<<dim3(QKV_N / 128, ROWS / 128), 256, GEMMH_SMEM>>>(
        xf, wqf, nullptr, qkvh, ROWS, QKV_N, DD);

    // 2) fused causal attention (fp16 tensor cores, 8 warps) -> fp16 ctx
    attn_f16<<<dim3(TT / 128, BB * HH), 256, ATT_SMEM>>>(qkvh, cf);

    // 3) output projection (fp16 MMA) -> fp32 out
    gemm_hf<0><<<dim3(DD / 128, ROWS / 128), 256, GEMMH_SMEM>>>(
        cf, wof, out, nullptr, ROWS, DD, DD);
}